// round 11
// baseline (speedup 1.0000x reference)
#include <cuda_runtime.h>
#include <cuda_bf16.h>
#include <math.h>
#include <cstdint>

#define SEQ   8192
#define BATCH 2
#define EMB   512
#define NH    8
#define DH    64
#define NBLK  128      // SEQ / 64
#define BLK   64
#define MBL   8        // gathered blocks per query block
#define NGLOB 2
#define NWIN  3

#define IN_STRIDE ((size_t)16384 * 512)

// ---- device-global scratch (allocation-free) ----
__device__ __nv_bfloat16 g_Inh[4 * IN_STRIDE];
__device__ __nv_bfloat16 g_Inl[4 * IN_STRIDE];
__device__ __nv_bfloat16 g_Qh[(size_t)BATCH * NH * SEQ * DH];
__device__ __nv_bfloat16 g_Ql[(size_t)BATCH * NH * SEQ * DH];
__device__ __nv_bfloat16 g_Kh[(size_t)BATCH * NH * SEQ * DH];
__device__ __nv_bfloat16 g_Kl[(size_t)BATCH * NH * SEQ * DH];
__device__ __nv_bfloat16 g_Vh[(size_t)BATCH * NH * SEQ * DH];
__device__ __nv_bfloat16 g_Vl[(size_t)BATCH * NH * SEQ * DH];
__device__ __nv_bfloat16 g_Whi[4u * 512u * 512u];
__device__ __nv_bfloat16 g_Wlo[4u * 512u * 512u];

// ============================================================
// helpers (baseline PTX only)
// ============================================================
__device__ __forceinline__ uint32_t smem_u32(const void* p) {
    uint32_t a;
    asm("{ .reg .u64 t; cvta.to.shared.u64 t, %1; cvt.u32.u64 %0, t; }"
        : "=r"(a) : "l"(p));
    return a;
}
__device__ __forceinline__ void ldm_x4(uint32_t* r, uint32_t addr) {
    asm volatile("ldmatrix.sync.aligned.m8n8.x4.shared.b16 {%0,%1,%2,%3}, [%4];"
                 : "=r"(r[0]), "=r"(r[1]), "=r"(r[2]), "=r"(r[3]) : "r"(addr));
}
__device__ __forceinline__ void ldm_x4t(uint32_t* r, uint32_t addr) {
    asm volatile("ldmatrix.sync.aligned.m8n8.x4.trans.shared.b16 {%0,%1,%2,%3}, [%4];"
                 : "=r"(r[0]), "=r"(r[1]), "=r"(r[2]), "=r"(r[3]) : "r"(addr));
}
__device__ __forceinline__ void mma_bf16(float* d, const uint32_t* a, const uint32_t* b) {
    asm volatile(
        "mma.sync.aligned.m16n8k16.row.col.f32.bf16.bf16.f32 "
        "{%0,%1,%2,%3}, {%4,%5,%6,%7}, {%8,%9}, {%0,%1,%2,%3};"
        : "+f"(d[0]), "+f"(d[1]), "+f"(d[2]), "+f"(d[3])
        : "r"(a[0]), "r"(a[1]), "r"(a[2]), "r"(a[3]), "r"(b[0]), "r"(b[1]));
}
__device__ __forceinline__ void cp16(uint32_t dst, const void* src) {
    asm volatile("cp.async.cg.shared.global [%0], [%1], 16;" :: "r"(dst), "l"(src) : "memory");
}
__device__ __forceinline__ void cp_commit() {
    asm volatile("cp.async.commit_group;" ::: "memory");
}
template<int N> __device__ __forceinline__ void cp_wait() {
    asm volatile("cp.async.wait_group %0;" :: "n"(N) : "memory");
}
__device__ __forceinline__ uint32_t pack_bf2(float x, float y) {
    __nv_bfloat162 v = __halves2bfloat162(__float2bfloat16(x), __float2bfloat16(y));
    return *(uint32_t*)&v;
}

// ============================================================
// Fused conversion: weights (fp32->hi/lo [mat][n][k]) + inputs.
// ============================================================
__global__ void conv_all(const float* __restrict__ qw, const float* __restrict__ kw,
                         const float* __restrict__ vw, const float* __restrict__ ow,
                         const float* __restrict__ qi, const float* __restrict__ ki,
                         const float* __restrict__ vi)
{
    const int bx = blockIdx.x;
    if (bx < 2048) {
        const int mat = bx >> 9;
        const int n   = bx & 511;
        const float* src = (mat == 0) ? qw : (mat == 1) ? kw : (mat == 2) ? vw : ow;
        for (int k = threadIdx.x; k < 512; k += 256) {
            float v;
            if (mat < 3) v = src[((size_t)(n >> 6) * 512 + k) * 64 + (n & 63)];
            else         v = src[(size_t)n * 512 + k];
            __nv_bfloat16 h = __float2bfloat16(v);
            __nv_bfloat16 l = __float2bfloat16(v - __bfloat162float(h));
            size_t o = (size_t)mat * 262144 + (size_t)n * 512 + k;
            g_Whi[o] = h;
            g_Wlo[o] = l;
        }
    } else {
        const int bi  = bx - 2048;
        const int mat = bi >> 11;
        const int blk = bi & 2047;
        const float* src = (mat == 0) ? qi : (mat == 1) ? ki : vi;
        __nv_bfloat16* dh = g_Inh + (size_t)mat * IN_STRIDE;
        __nv_bfloat16* dl = g_Inl + (size_t)mat * IN_STRIDE;
#pragma unroll
        for (int i = 0; i < 4; i++) {
            size_t o4 = (size_t)blk * 1024 + i * 256 + threadIdx.x;
            float4 x = *(const float4*)&src[o4 * 4];
            __nv_bfloat16 h0 = __float2bfloat16(x.x);
            __nv_bfloat16 h1 = __float2bfloat16(x.y);
            __nv_bfloat16 h2 = __float2bfloat16(x.z);
            __nv_bfloat16 h3 = __float2bfloat16(x.w);
            __nv_bfloat16 l0 = __float2bfloat16(x.x - __bfloat162float(h0));
            __nv_bfloat16 l1 = __float2bfloat16(x.y - __bfloat162float(h1));
            __nv_bfloat16 l2 = __float2bfloat16(x.z - __bfloat162float(h2));
            __nv_bfloat16 l3 = __float2bfloat16(x.w - __bfloat162float(h3));
            *(__nv_bfloat162*)&dh[o4 * 4 + 0] = __halves2bfloat162(h0, h1);
            *(__nv_bfloat162*)&dh[o4 * 4 + 2] = __halves2bfloat162(h2, h3);
            *(__nv_bfloat162*)&dl[o4 * 4 + 0] = __halves2bfloat162(l0, l1);
            *(__nv_bfloat162*)&dl[o4 * 4 + 2] = __halves2bfloat162(l2, l3);
        }
    }
}

// ============================================================
// HMMA GEMM v2: 128 threads, 4 warps, warp tile 64x64 (2x2 grid).
// Halves A/B fragment re-reads vs the 2x4 grid (48KB -> 32KB smem read
// per k16 per CTA) -> tensor-bound instead of LDSM-bound.
// bf16 hi/lo 3-term, 3-stage cp.async pipeline, BK=32.
// ============================================================
#define GS_STAGE 32768
#define GS_SMEM  (3 * GS_STAGE)

__global__ __launch_bounds__(128)
void gemm_mma(const float* __restrict__ qb, const float* __restrict__ kb,
              const float* __restrict__ vb, const float* __restrict__ ob,
              float* __restrict__ Cout, int mode_base)
{
    extern __shared__ char gsm[];
    const uint32_t sb = smem_u32(gsm);
    const int tid  = threadIdx.x;
    const int wid  = tid >> 5;
    const int lane = tid & 31;
    const int wm   = wid >> 1;          // 0..1 (64 rows each)
    const int wn   = wid & 1;           // 0..1 (64 cols each)
    const int m0   = blockIdx.x * 128;
    const int mode = mode_base + (blockIdx.y >> 2);
    const int n0   = (blockIdx.y & 3) * 128;

    const __nv_bfloat16* __restrict__ Ah = g_Inh + (size_t)mode * IN_STRIDE;
    const __nv_bfloat16* __restrict__ Al = g_Inl + (size_t)mode * IN_STRIDE;
    const __nv_bfloat16* __restrict__ Bh = g_Whi + (size_t)mode * 262144;
    const __nv_bfloat16* __restrict__ Bl = g_Wlo + (size_t)mode * 262144;
    const float* __restrict__ bias = (mode == 0) ? qb : (mode == 1) ? kb
                                   : (mode == 2) ? vb : ob;

    // stage layout: Ah 0-8K, Al 8-16K, Bh 16-24K, Bl 24-32K (64B rows, swizzled)
#define GPREFETCH(K0, ST)                                                        \
    {                                                                            \
        uint32_t d0 = sb + (ST) * GS_STAGE;                                      \
        _Pragma("unroll")                                                        \
        for (int i = 0; i < 16; i++) {                                           \
            int idx = tid + 128 * i;                                             \
            int mt  = idx >> 9;                                                  \
            int row = (idx >> 2) & 127;                                          \
            int seg = idx & 3;                                                   \
            const __nv_bfloat16* src =                                           \
                (mt == 0) ? Ah + (size_t)(m0 + row) * 512 + (K0) + seg * 8 :     \
                (mt == 1) ? Al + (size_t)(m0 + row) * 512 + (K0) + seg * 8 :     \
                (mt == 2) ? Bh + (size_t)(n0 + row) * 512 + (K0) + seg * 8 :     \
                            Bl + (size_t)(n0 + row) * 512 + (K0) + seg * 8;      \
            cp16(d0 + mt * 8192 + row * 64 + ((seg ^ ((row >> 1) & 3)) << 4),    \
                 src);                                                           \
        }                                                                        \
    }

    GPREFETCH(0, 0);  cp_commit();
    GPREFETCH(32, 1); cp_commit();

    float acc[4][8][4];
#pragma unroll
    for (int i = 0; i < 4; i++)
#pragma unroll
        for (int j = 0; j < 8; j++)
#pragma unroll
            for (int r = 0; r < 4; r++) acc[i][j][r] = 0.f;

    const int tile = lane >> 3;
    const int r8   = lane & 7;

    for (int it = 0; it < 16; it++) {
        if (it < 15) cp_wait<1>(); else cp_wait<0>();
        __syncthreads();
        if (it + 2 < 16) {
            int st = (it + 2) % 3;
            GPREFETCH((it + 2) * 32, st);
            cp_commit();
        }
        const uint32_t stg  = sb + (it % 3) * GS_STAGE;
        const uint32_t aAhi = stg;
        const uint32_t aAlo = stg + 8192;
        const uint32_t aBhi = stg + 16384;
        const uint32_t aBlo = stg + 24576;

#pragma unroll
        for (int ks = 0; ks < 2; ks++) {
            const int k16 = ks * 16;
            const int arow_off = r8 + ((tile & 1) << 3);
            const int aseg = (k16 + ((tile >= 2) ? 8 : 0)) >> 3;
            const int brow_off = r8 + ((tile >> 1) << 3);
            const int bseg = (k16 + ((tile & 1) ? 8 : 0)) >> 3;

            // ---- all 16 ldmatrix for this k16 ----
            uint32_t ah[4][4], al[4][4], bh[4][4], bl[4][4];
#pragma unroll
            for (int mi = 0; mi < 4; mi++) {
                int row = wm * 64 + mi * 16 + arow_off;
                uint32_t off = (uint32_t)(row * 64 + ((aseg ^ ((row >> 1) & 3)) << 4));
                ldm_x4(ah[mi], aAhi + off);
                ldm_x4(al[mi], aAlo + off);
            }
#pragma unroll
            for (int bi = 0; bi < 4; bi++) {
                int row = wn * 64 + bi * 16 + brow_off;
                uint32_t off = (uint32_t)(row * 64 + ((bseg ^ ((row >> 1) & 3)) << 4));
                ldm_x4(bh[bi], aBhi + off);
                ldm_x4(bl[bi], aBlo + off);
            }

            // ---- 96 MMAs ----
#pragma unroll
            for (int mi = 0; mi < 4; mi++)
#pragma unroll
                for (int ni = 0; ni < 8; ni++)
                    mma_bf16(acc[mi][ni], ah[mi], &bh[ni >> 1][(ni & 1) * 2]);
#pragma unroll
            for (int mi = 0; mi < 4; mi++)
#pragma unroll
                for (int ni = 0; ni < 8; ni++)
                    mma_bf16(acc[mi][ni], ah[mi], &bl[ni >> 1][(ni & 1) * 2]);
#pragma unroll
            for (int mi = 0; mi < 4; mi++)
#pragma unroll
                for (int ni = 0; ni < 8; ni++)
                    mma_bf16(acc[mi][ni], al[mi], &bh[ni >> 1][(ni & 1) * 2]);
        }
    }

    // ---- epilogue ----
    const int mrb = m0 + wm * 64;
    const int ncb = n0 + wn * 64;
#pragma unroll
    for (int mi = 0; mi < 4; mi++) {
#pragma unroll
        for (int ni = 0; ni < 8; ni++) {
            int n = ncb + ni * 8 + (lane & 3) * 2;
            float2 bv = *(const float2*)&bias[n];
#pragma unroll
            for (int hf = 0; hf < 2; hf++) {
                int m = mrb + mi * 16 + (lane >> 2) + hf * 8;
                float c0 = acc[mi][ni][hf * 2 + 0] + bv.x;
                float c1 = acc[mi][ni][hf * 2 + 1] + bv.y;
                if (mode < 3) {
                    int bb = m & 1, s = m >> 1;
                    int hh = n >> 6, d = n & 63;
                    size_t addr = (((size_t)bb * NH + hh) * SEQ + s) * DH + d;
                    __nv_bfloat16 h0 = __float2bfloat16(c0);
                    __nv_bfloat16 h1 = __float2bfloat16(c1);
                    __nv_bfloat16 e0 = __float2bfloat16(c0 - __bfloat162float(h0));
                    __nv_bfloat16 e1 = __float2bfloat16(c1 - __bfloat162float(h1));
                    __nv_bfloat16* Ch = (mode == 0) ? g_Qh : (mode == 1) ? g_Kh : g_Vh;
                    __nv_bfloat16* Cl = (mode == 0) ? g_Ql : (mode == 1) ? g_Kl : g_Vl;
                    *(__nv_bfloat162*)&Ch[addr] = __halves2bfloat162(h0, h1);
                    *(__nv_bfloat162*)&Cl[addr] = __halves2bfloat162(e0, e1);
                } else {
                    int bb = m >> 13, s = m & (SEQ - 1);
                    *(float2*)&Cout[(size_t)(s * BATCH + bb) * EMB + n] = make_float2(c0, c1);
                }
            }
        }
    }
#undef GPREFETCH
}

// ============================================================
// Attention v3 (R9-proven): 128 threads, 4 warps; warp = 16 q-rows x 64 keys.
// ============================================================
#define AT_K0 0
#define AT_K1 16384
#define AT_V  32768

__device__ __forceinline__ int blk_of(int j, int nb, const int* __restrict__ ri) {
    if (j < NGLOB) return j;
    if (j < NGLOB + NWIN) return (nb + j - 3 + NBLK) & (NBLK - 1);
    return ri[nb * 3 + (j - 5)];
}

__global__ __launch_bounds__(128, 3)
void attn_mma(const int* __restrict__ rand_idx)
{
    __shared__ char smb[49152];
    const uint32_t sb = smem_u32(smb);

    const int nb  = blockIdx.x;
    const int bh  = blockIdx.y;
    const int tid = threadIdx.x;
    const int w    = tid >> 5;
    const int lane = tid & 31;
    const int tile = lane >> 3;
    const int r8   = lane & 7;
    const int sel  = lane >> 3;
    const int qrow = lane >> 2;
    const int qc   = (lane & 3) * 2;
    const size_t base = (size_t)bh * SEQ * DH;
    const float CC = 0.18033688011112042f;

#define STAGE_HL(DST, SRCH, SRCL, ROWBASE)                                       \
    {                                                                            \
        _Pragma("unroll")                                                        \
        for (int i = 0; i < 8; i++) {                                            \
            int idx = tid + 128 * i;                                             \
            int mh  = idx >> 9;                                                  \
            int row = (idx >> 3) & 63;                                           \
            int seg = idx & 7;                                                   \
            const __nv_bfloat16* src = (mh ? (SRCL) : (SRCH)) + (ROWBASE)        \
                                       + (size_t)row * 64 + seg * 8;             \
            cp16((DST) + mh * 8192 + row * 128 + ((seg ^ (row & 7)) << 4), src); \
        }                                                                        \
    }

    STAGE_HL(sb + AT_V,  g_Qh, g_Ql, base + (size_t)nb * BLK * DH);
    STAGE_HL(sb + AT_K0, g_Kh, g_Kl, base + (size_t)blk_of(0, nb, rand_idx) * BLK * DH);
    cp_commit();
    cp_wait<0>();
    __syncthreads();

    uint32_t qh[4][4], ql[4][4];
#pragma unroll
    for (int ks = 0; ks < 4; ks++) {
        const int arow = 16 * w + r8 + ((tile & 1) << 3);
        const int aseg = ks * 2 + ((tile >> 1) & 1);
        const uint32_t aoff = (uint32_t)(arow * 128 + ((aseg ^ (arow & 7)) << 4));
        ldm_x4(qh[ks], sb + AT_V + aoff);
        ldm_x4(ql[ks], sb + AT_V + 8192 + aoff);
    }
    __syncthreads();

    STAGE_HL(sb + AT_V,  g_Vh, g_Vl, base + (size_t)blk_of(0, nb, rand_idx) * BLK * DH);
    cp_commit();
    STAGE_HL(sb + AT_K1, g_Kh, g_Kl, base + (size_t)blk_of(1, nb, rand_idx) * BLK * DH);
    cp_commit();

    float of[8][4];
#pragma unroll
    for (int i = 0; i < 8; i++)
#pragma unroll
        for (int jj = 0; jj < 4; jj++) of[i][jj] = 0.f;
    float mst0 = -1e30f, mst1 = -1e30f, lst0 = 0.f, lst1 = 0.f;

    for (int j = 0; j < MBL; j++) {
        const uint32_t kbuf = sb + ((j & 1) ? AT_K1 : AT_K0);

        float sf[8][4];
#pragma unroll
        for (int nf = 0; nf < 8; nf++)
#pragma unroll
            for (int r = 0; r < 4; r++) sf[nf][r] = 0.f;

#pragma unroll
        for (int ks = 0; ks < 4; ks++) {
            uint32_t kh[4][4], kl[4][4];
#pragma unroll
            for (int p = 0; p < 4; p++) {
                const int brow = 16 * p + r8 + ((tile >> 1) << 3);
                const int bseg = ks * 2 + (tile & 1);
                const uint32_t boff = (uint32_t)(brow * 128 + ((bseg ^ (brow & 7)) << 4));
                ldm_x4(kh[p], kbuf + boff);
                ldm_x4(kl[p], kbuf + 8192 + boff);
            }
#pragma unroll
            for (int nf = 0; nf < 8; nf++)
                mma_bf16(sf[nf], qh[ks], &kh[nf >> 1][(nf & 1) * 2]);
#pragma unroll
            for (int nf = 0; nf < 8; nf++)
                mma_bf16(sf[nf], qh[ks], &kl[nf >> 1][(nf & 1) * 2]);
#pragma unroll
            for (int nf = 0; nf < 8; nf++)
                mma_bf16(sf[nf], ql[ks], &kh[nf >> 1][(nf & 1) * 2]);
        }

        float rmax0 = sf[0][0], rmax1 = sf[0][2];
#pragma unroll
        for (int nf = 0; nf < 8; nf++) {
            rmax0 = fmaxf(rmax0, fmaxf(sf[nf][0], sf[nf][1]));
            rmax1 = fmaxf(rmax1, fmaxf(sf[nf][2], sf[nf][3]));
        }
        rmax0 = fmaxf(rmax0, __shfl_xor_sync(0xffffffffu, rmax0, 1));
        rmax0 = fmaxf(rmax0, __shfl_xor_sync(0xffffffffu, rmax0, 2));
        rmax1 = fmaxf(rmax1, __shfl_xor_sync(0xffffffffu, rmax1, 1));
        rmax1 = fmaxf(rmax1, __shfl_xor_sync(0xffffffffu, rmax1, 2));
        const float mn0 = fmaxf(mst0, rmax0);
        const float mn1 = fmaxf(mst1, rmax1);
        const float al0 = exp2f((mst0 - mn0) * CC);
        const float al1 = exp2f((mst1 - mn1) * CC);

        float rsum0 = 0.f, rsum1 = 0.f;
        uint32_t pah[4][4], pal[4][4];
#pragma unroll
        for (int t = 0; t < 4; t++) {
#pragma unroll
            for (int hl = 0; hl < 2; hl++) {
                int nf = 2 * t + hl;
                float p0 = exp2f((sf[nf][0] - mn0) * CC);
                float p1 = exp2f((sf[nf][1] - mn0) * CC);
                float p2 = exp2f((sf[nf][2] - mn1) * CC);
                float p3 = exp2f((sf[nf][3] - mn1) * CC);
                rsum0 += p0 + p1;
                rsum1 += p2 + p3;
                uint32_t h01 = pack_bf2(p0, p1);
                uint32_t h23 = pack_bf2(p2, p3);
                __nv_bfloat162 hv01 = *(__nv_bfloat162*)&h01;
                __nv_bfloat162 hv23 = *(__nv_bfloat162*)&h23;
                pah[t][2 * hl + 0] = h01;
                pah[t][2 * hl + 1] = h23;
                pal[t][2 * hl + 0] = pack_bf2(p0 - __bfloat162float(hv01.x),
                                              p1 - __bfloat162float(hv01.y));
                pal[t][2 * hl + 1] = pack_bf2(p2 - __bfloat162float(hv23.x),
                                              p3 - __bfloat162float(hv23.y));
            }
        }
        rsum0 += __shfl_xor_sync(0xffffffffu, rsum0, 1);
        rsum0 += __shfl_xor_sync(0xffffffffu, rsum0, 2);
        rsum1 += __shfl_xor_sync(0xffffffffu, rsum1, 1);
        rsum1 += __shfl_xor_sync(0xffffffffu, rsum1, 2);
        lst0 = lst0 * al0 + rsum0;
        lst1 = lst1 * al1 + rsum1;
        mst0 = mn0;
        mst1 = mn1;
#pragma unroll
        for (int nf = 0; nf < 8; nf++) {
            of[nf][0] *= al0; of[nf][1] *= al0;
            of[nf][2] *= al1; of[nf][3] *= al1;
        }

        if (j < MBL - 1) cp_wait<1>(); else cp_wait<0>();
        __syncthreads();

#pragma unroll
        for (int t = 0; t < 4; t++) {
            const int vkey = 16 * t + (lane & 7) + ((sel & 1) << 3);
#pragma unroll
            for (int g = 0; g < 4; g++) {
                const int vseg = 2 * g + (sel >> 1);
                const uint32_t voff = (uint32_t)(vkey * 128 + ((vseg ^ (vkey & 7)) << 4));
                uint32_t vh[4], vl[4];
                ldm_x4t(vh, sb + AT_V + voff);
                ldm_x4t(vl, sb + AT_V + 8192 + voff);
                mma_bf16(of[2 * g + 0], pah[t], &vh[0]);
                mma_bf16(of[2 * g + 1], pah[t], &vh[2]);
                mma_bf16(of[2 * g + 0], pal[t], &vh[0]);
                mma_bf16(of[2 * g + 1], pal[t], &vh[2]);
                mma_bf16(of[2 * g + 0], pah[t], &vl[0]);
                mma_bf16(of[2 * g + 1], pah[t], &vl[2]);
            }
        }

        if (j < MBL - 1) {
            cp_wait<0>();
            __syncthreads();
            size_t v_b = base + (size_t)blk_of(j + 1, nb, rand_idx) * BLK * DH;
            STAGE_HL(sb + AT_V, g_Vh, g_Vl, v_b);
            cp_commit();
            if (j < MBL - 2) {
                size_t k_b = base + (size_t)blk_of(j + 2, nb, rand_idx) * BLK * DH;
                STAGE_HL(sb + ((j & 1) ? AT_K1 : AT_K0), g_Kh, g_Kl, k_b);
                cp_commit();
            }
        }
    }

    const int b = bh >> 3, h = bh & 7;
    const int r0 = 16 * w + qrow;
    const float inv0 = 1.f / lst0;
    const float inv1 = 1.f / lst1;
    __nv_bfloat16* AOh = g_Inh + 3 * IN_STRIDE;
    __nv_bfloat16* AOl = g_Inl + 3 * IN_STRIDE;
#pragma unroll
    for (int nf = 0; nf < 8; nf++) {
        int d = nf * 8 + qc;
        float v00 = of[nf][0] * inv0, v01 = of[nf][1] * inv0;
        float v10 = of[nf][2] * inv1, v11 = of[nf][3] * inv1;
        size_t a0 = (size_t)(b * SEQ + nb * BLK + r0) * EMB + h * DH + d;
        size_t a1 = (size_t)(b * SEQ + nb * BLK + r0 + 8) * EMB + h * DH + d;
        __nv_bfloat16 h00 = __float2bfloat16(v00), h01 = __float2bfloat16(v01);
        __nv_bfloat16 h10 = __float2bfloat16(v10), h11 = __float2bfloat16(v11);
        *(__nv_bfloat162*)&AOh[a0] = __halves2bfloat162(h00, h01);
        *(__nv_bfloat162*)&AOh[a1] = __halves2bfloat162(h10, h11);
        *(__nv_bfloat162*)&AOl[a0] = __halves2bfloat162(
            __float2bfloat16(v00 - __bfloat162float(h00)),
            __float2bfloat16(v01 - __bfloat162float(h01)));
        *(__nv_bfloat162*)&AOl[a1] = __halves2bfloat162(
            __float2bfloat16(v10 - __bfloat162float(h10)),
            __float2bfloat16(v11 - __bfloat162float(h11)));
    }
#undef STAGE_HL
}

// ============================================================
extern "C" void kernel_launch(void* const* d_in, const int* in_sizes, int n_in,
                              void* d_out, int out_size)
{
    const float* query   = (const float*)d_in[0];
    const float* key_inp = (const float*)d_in[1];
    const float* value   = (const float*)d_in[2];
    const float* q_w     = (const float*)d_in[3];
    const float* k_w     = (const float*)d_in[4];
    const float* v_w     = (const float*)d_in[5];
    const float* q_b     = (const float*)d_in[6];
    const float* k_b     = (const float*)d_in[7];
    const float* v_b     = (const float*)d_in[8];
    const float* out_w   = (const float*)d_in[9];
    const float* out_b   = (const float*)d_in[10];
    const int*   rand_idx= (const int*)d_in[11];
    float* out = (float*)d_out;

    static bool attr_set = false;
    if (!attr_set) {
        cudaFuncSetAttribute(gemm_mma,
                             cudaFuncAttributeMaxDynamicSharedMemorySize, GS_SMEM);
        attr_set = true;
    }

    conv_all<<<8192, 256>>>(q_w, k_w, v_w, out_w, query, key_inp, value);

    dim3 gQKV(128, 12);
    gemm_mma<<<gQKV, 128, GS_SMEM>>>(q_b, k_b, v_b, out_b, out, 0);

    dim3 gAttn(NBLK, BATCH * NH);
    attn_mma<<<gAttn, 128>>>(rand_idx);

    dim3 gOut(128, 4);
    gemm_mma<<<gOut, 128, GS_SMEM>>>(q_b, k_b, v_b, out_b, out, 3);
}

// round 12
// speedup vs baseline: 1.7566x; 1.7566x over previous
#include <cuda_runtime.h>
#include <cuda_bf16.h>
#include <cuda_fp16.h>
#include <math.h>
#include <cstdint>

#define SEQ   8192
#define BATCH 2
#define EMB   512
#define NH    8
#define DH    64
#define NBLK  128      // SEQ / 64
#define BLK   64
#define MBL   8        // gathered blocks per query block
#define NGLOB 2
#define NWIN  3

#define IN_STRIDE ((size_t)16384 * 512)

// ---- device-global scratch (allocation-free) ----
// A-side activations, fp16 hi/lo: slots 0=q_in 1=k_in 2=v_in 3=attn_out
__device__ __half g_Inh[4 * IN_STRIDE];
__device__ __half g_Inl[4 * IN_STRIDE];
// Q/K/V (post-projection) bf16 hi/lo, [b][h][s][d]  (attention path, unchanged)
__device__ __nv_bfloat16 g_Qh[(size_t)BATCH * NH * SEQ * DH];
__device__ __nv_bfloat16 g_Ql[(size_t)BATCH * NH * SEQ * DH];
__device__ __nv_bfloat16 g_Kh[(size_t)BATCH * NH * SEQ * DH];
__device__ __nv_bfloat16 g_Kl[(size_t)BATCH * NH * SEQ * DH];
__device__ __nv_bfloat16 g_Vh[(size_t)BATCH * NH * SEQ * DH];
__device__ __nv_bfloat16 g_Vl[(size_t)BATCH * NH * SEQ * DH];
// fp16 single weights: [mat][n][k], mat: 0=q 1=k 2=v 3=out
__device__ __half g_Wh[4u * 512u * 512u];

// ============================================================
// helpers (baseline PTX only)
// ============================================================
__device__ __forceinline__ uint32_t smem_u32(const void* p) {
    uint32_t a;
    asm("{ .reg .u64 t; cvta.to.shared.u64 t, %1; cvt.u32.u64 %0, t; }"
        : "=r"(a) : "l"(p));
    return a;
}
__device__ __forceinline__ void ldm_x4(uint32_t* r, uint32_t addr) {
    asm volatile("ldmatrix.sync.aligned.m8n8.x4.shared.b16 {%0,%1,%2,%3}, [%4];"
                 : "=r"(r[0]), "=r"(r[1]), "=r"(r[2]), "=r"(r[3]) : "r"(addr));
}
__device__ __forceinline__ void ldm_x4t(uint32_t* r, uint32_t addr) {
    asm volatile("ldmatrix.sync.aligned.m8n8.x4.trans.shared.b16 {%0,%1,%2,%3}, [%4];"
                 : "=r"(r[0]), "=r"(r[1]), "=r"(r[2]), "=r"(r[3]) : "r"(addr));
}
__device__ __forceinline__ void mma_bf16(float* d, const uint32_t* a, const uint32_t* b) {
    asm volatile(
        "mma.sync.aligned.m16n8k16.row.col.f32.bf16.bf16.f32 "
        "{%0,%1,%2,%3}, {%4,%5,%6,%7}, {%8,%9}, {%0,%1,%2,%3};"
        : "+f"(d[0]), "+f"(d[1]), "+f"(d[2]), "+f"(d[3])
        : "r"(a[0]), "r"(a[1]), "r"(a[2]), "r"(a[3]), "r"(b[0]), "r"(b[1]));
}
__device__ __forceinline__ void mma_fp16(float* d, const uint32_t* a, const uint32_t* b) {
    asm volatile(
        "mma.sync.aligned.m16n8k16.row.col.f32.f16.f16.f32 "
        "{%0,%1,%2,%3}, {%4,%5,%6,%7}, {%8,%9}, {%0,%1,%2,%3};"
        : "+f"(d[0]), "+f"(d[1]), "+f"(d[2]), "+f"(d[3])
        : "r"(a[0]), "r"(a[1]), "r"(a[2]), "r"(a[3]), "r"(b[0]), "r"(b[1]));
}
__device__ __forceinline__ void cp16(uint32_t dst, const void* src) {
    asm volatile("cp.async.cg.shared.global [%0], [%1], 16;" :: "r"(dst), "l"(src) : "memory");
}
__device__ __forceinline__ void cp_commit() {
    asm volatile("cp.async.commit_group;" ::: "memory");
}
template<int N> __device__ __forceinline__ void cp_wait() {
    asm volatile("cp.async.wait_group %0;" :: "n"(N) : "memory");
}
__device__ __forceinline__ uint32_t pack_bf2(float x, float y) {
    __nv_bfloat162 v = __halves2bfloat162(__float2bfloat16(x), __float2bfloat16(y));
    return *(uint32_t*)&v;
}

// ============================================================
// Fused conversion: weights (fp32 -> single fp16, [mat][n][k]) +
// inputs (fp32 -> fp16 hi/lo).  blocks [0,2048): weights; [2048,8192): inputs.
// ============================================================
__global__ void conv_all(const float* __restrict__ qw, const float* __restrict__ kw,
                         const float* __restrict__ vw, const float* __restrict__ ow,
                         const float* __restrict__ qi, const float* __restrict__ ki,
                         const float* __restrict__ vi)
{
    const int bx = blockIdx.x;
    if (bx < 2048) {
        const int mat = bx >> 9;
        const int n   = bx & 511;
        const float* src = (mat == 0) ? qw : (mat == 1) ? kw : (mat == 2) ? vw : ow;
        for (int k = threadIdx.x; k < 512; k += 256) {
            float v;
            if (mat < 3) v = src[((size_t)(n >> 6) * 512 + k) * 64 + (n & 63)];
            else         v = src[(size_t)n * 512 + k];
            g_Wh[(size_t)mat * 262144 + (size_t)n * 512 + k] = __float2half(v);
        }
    } else {
        const int bi  = bx - 2048;
        const int mat = bi >> 11;
        const int blk = bi & 2047;
        const float* src = (mat == 0) ? qi : (mat == 1) ? ki : vi;
        __half* dh = g_Inh + (size_t)mat * IN_STRIDE;
        __half* dl = g_Inl + (size_t)mat * IN_STRIDE;
#pragma unroll
        for (int i = 0; i < 4; i++) {
            size_t o4 = (size_t)blk * 1024 + i * 256 + threadIdx.x;
            float4 x = *(const float4*)&src[o4 * 4];
            __half h0 = __float2half(x.x), h1 = __float2half(x.y);
            __half h2 = __float2half(x.z), h3 = __float2half(x.w);
            __half l0 = __float2half(x.x - __half2float(h0));
            __half l1 = __float2half(x.y - __half2float(h1));
            __half l2 = __float2half(x.z - __half2float(h2));
            __half l3 = __float2half(x.w - __half2float(h3));
            *(__half2*)&dh[o4 * 4 + 0] = __halves2half2(h0, h1);
            *(__half2*)&dh[o4 * 4 + 2] = __halves2half2(h2, h3);
            *(__half2*)&dl[o4 * 4 + 0] = __halves2half2(l0, l1);
            *(__half2*)&dl[o4 * 4 + 2] = __halves2half2(l2, l3);
        }
    }
}

// ============================================================
// HMMA GEMM, fp16 2-term (A split hi/lo, weights single fp16).
// C = A[16384x512] * W^T. CTA 128x128, BK=32, 256 thr, warp 64x32 (2x4).
// 3-stage cp.async pipeline. Stage: Ah 8K | Al 8K | B 8K = 24KB.
// ============================================================
#define GS_STAGE 24576
#define GS_SMEM  (3 * GS_STAGE)

__global__ __launch_bounds__(256, 2)
void gemm_mma(const float* __restrict__ qb, const float* __restrict__ kb,
              const float* __restrict__ vb, const float* __restrict__ ob,
              float* __restrict__ Cout, int mode_base)
{
    extern __shared__ char gsm[];
    const uint32_t sb = smem_u32(gsm);
    const int tid  = threadIdx.x;
    const int wid  = tid >> 5;
    const int lane = tid & 31;
    const int wm   = wid >> 2;
    const int wn   = wid & 3;
    const int m0   = blockIdx.x * 128;
    const int mode = mode_base + (blockIdx.y >> 2);
    const int n0   = (blockIdx.y & 3) * 128;

    const __half* __restrict__ Ah = g_Inh + (size_t)mode * IN_STRIDE;
    const __half* __restrict__ Al = g_Inl + (size_t)mode * IN_STRIDE;
    const __half* __restrict__ Bw = g_Wh  + (size_t)mode * 262144;
    const float* __restrict__ bias = (mode == 0) ? qb : (mode == 1) ? kb
                                   : (mode == 2) ? vb : ob;

    // stage layout: Ah 0-8K, Al 8-16K, B 16-24K (64B rows, swizzled)
#define GPREFETCH(K0, ST)                                                        \
    {                                                                            \
        uint32_t d0 = sb + (ST) * GS_STAGE;                                      \
        _Pragma("unroll")                                                        \
        for (int i = 0; i < 6; i++) {                                            \
            int idx = tid + 256 * i;                                             \
            int mt  = idx >> 9;                                                  \
            int row = (idx >> 2) & 127;                                          \
            int seg = idx & 3;                                                   \
            const __half* src =                                                  \
                (mt == 0) ? Ah + (size_t)(m0 + row) * 512 + (K0) + seg * 8 :     \
                (mt == 1) ? Al + (size_t)(m0 + row) * 512 + (K0) + seg * 8 :     \
                            Bw + (size_t)(n0 + row) * 512 + (K0) + seg * 8;      \
            cp16(d0 + mt * 8192 + row * 64 + ((seg ^ ((row >> 1) & 3)) << 4),    \
                 src);                                                           \
        }                                                                        \
    }

    GPREFETCH(0, 0);  cp_commit();
    GPREFETCH(32, 1); cp_commit();

    float acc[4][4][4];
#pragma unroll
    for (int i = 0; i < 4; i++)
#pragma unroll
        for (int j = 0; j < 4; j++)
#pragma unroll
            for (int r = 0; r < 4; r++) acc[i][j][r] = 0.f;

    const int tile = lane >> 3;
    const int r8   = lane & 7;

    for (int it = 0; it < 16; it++) {
        if (it < 15) cp_wait<1>(); else cp_wait<0>();
        __syncthreads();
        if (it + 2 < 16) {
            int st = (it + 2) % 3;
            GPREFETCH((it + 2) * 32, st);
            cp_commit();
        }
        const uint32_t stg  = sb + (it % 3) * GS_STAGE;
        const uint32_t aAhi = stg;
        const uint32_t aAlo = stg + 8192;
        const uint32_t aB   = stg + 16384;

#pragma unroll
        for (int ks = 0; ks < 2; ks++) {
            const int k16 = ks * 16;
            const int arow_off = r8 + ((tile & 1) << 3);
            const int aseg = (k16 + ((tile >= 2) ? 8 : 0)) >> 3;
            const int brow_off = r8 + ((tile >> 1) << 3);
            const int bseg = (k16 + ((tile & 1) ? 8 : 0)) >> 3;

            uint32_t ah[4][4], al[4][4], bf[2][4];
#pragma unroll
            for (int mi = 0; mi < 4; mi++) {
                int row = wm * 64 + mi * 16 + arow_off;
                uint32_t off = (uint32_t)(row * 64 + ((aseg ^ ((row >> 1) & 3)) << 4));
                ldm_x4(ah[mi], aAhi + off);
                ldm_x4(al[mi], aAlo + off);
            }
#pragma unroll
            for (int p = 0; p < 2; p++) {
                int row = wn * 32 + p * 16 + brow_off;
                uint32_t off = (uint32_t)(row * 64 + ((bseg ^ ((row >> 1) & 3)) << 4));
                ldm_x4(bf[p], aB + off);
            }

#pragma unroll
            for (int mi = 0; mi < 4; mi++)
#pragma unroll
                for (int ni = 0; ni < 4; ni++)
                    mma_fp16(acc[mi][ni], ah[mi], &bf[ni >> 1][(ni & 1) * 2]);
#pragma unroll
            for (int mi = 0; mi < 4; mi++)
#pragma unroll
                for (int ni = 0; ni < 4; ni++)
                    mma_fp16(acc[mi][ni], al[mi], &bf[ni >> 1][(ni & 1) * 2]);
        }
    }

    const int mrb = m0 + wm * 64;
    const int ncb = n0 + wn * 32;
#pragma unroll
    for (int mi = 0; mi < 4; mi++) {
#pragma unroll
        for (int ni = 0; ni < 4; ni++) {
            int n = ncb + ni * 8 + (lane & 3) * 2;
            float2 bv = *(const float2*)&bias[n];
#pragma unroll
            for (int hf = 0; hf < 2; hf++) {
                int m = mrb + mi * 16 + (lane >> 2) + hf * 8;
                float c0 = acc[mi][ni][hf * 2 + 0] + bv.x;
                float c1 = acc[mi][ni][hf * 2 + 1] + bv.y;
                if (mode < 3) {
                    int bb = m & 1, s = m >> 1;
                    int hh = n >> 6, d = n & 63;
                    size_t addr = (((size_t)bb * NH + hh) * SEQ + s) * DH + d;
                    __nv_bfloat16 h0 = __float2bfloat16(c0);
                    __nv_bfloat16 h1 = __float2bfloat16(c1);
                    __nv_bfloat16 e0 = __float2bfloat16(c0 - __bfloat162float(h0));
                    __nv_bfloat16 e1 = __float2bfloat16(c1 - __bfloat162float(h1));
                    __nv_bfloat16* Ch = (mode == 0) ? g_Qh : (mode == 1) ? g_Kh : g_Vh;
                    __nv_bfloat16* Cl = (mode == 0) ? g_Ql : (mode == 1) ? g_Kl : g_Vl;
                    *(__nv_bfloat162*)&Ch[addr] = __halves2bfloat162(h0, h1);
                    *(__nv_bfloat162*)&Cl[addr] = __halves2bfloat162(e0, e1);
                } else {
                    int bb = m >> 13, s = m & (SEQ - 1);
                    *(float2*)&Cout[(size_t)(s * BATCH + bb) * EMB + n] = make_float2(c0, c1);
                }
            }
        }
    }
#undef GPREFETCH
}

// ============================================================
// Attention v3 (R9-proven, bf16 3-term): 128 threads, 4 warps;
// warp = 16 q-rows x 64 keys. Epilogue now writes AO as fp16 hi/lo.
// ============================================================
#define AT_K0 0
#define AT_K1 16384
#define AT_V  32768

__device__ __forceinline__ int blk_of(int j, int nb, const int* __restrict__ ri) {
    if (j < NGLOB) return j;
    if (j < NGLOB + NWIN) return (nb + j - 3 + NBLK) & (NBLK - 1);
    return ri[nb * 3 + (j - 5)];
}

__global__ __launch_bounds__(128, 3)
void attn_mma(const int* __restrict__ rand_idx)
{
    __shared__ char smb[49152];
    const uint32_t sb = smem_u32(smb);

    const int nb  = blockIdx.x;
    const int bh  = blockIdx.y;
    const int tid = threadIdx.x;
    const int w    = tid >> 5;
    const int lane = tid & 31;
    const int tile = lane >> 3;
    const int r8   = lane & 7;
    const int sel  = lane >> 3;
    const int qrow = lane >> 2;
    const int qc   = (lane & 3) * 2;
    const size_t base = (size_t)bh * SEQ * DH;
    const float CC = 0.18033688011112042f;

#define STAGE_HL(DST, SRCH, SRCL, ROWBASE)                                       \
    {                                                                            \
        _Pragma("unroll")                                                        \
        for (int i = 0; i < 8; i++) {                                            \
            int idx = tid + 128 * i;                                             \
            int mh  = idx >> 9;                                                  \
            int row = (idx >> 3) & 63;                                           \
            int seg = idx & 7;                                                   \
            const __nv_bfloat16* src = (mh ? (SRCL) : (SRCH)) + (ROWBASE)        \
                                       + (size_t)row * 64 + seg * 8;             \
            cp16((DST) + mh * 8192 + row * 128 + ((seg ^ (row & 7)) << 4), src); \
        }                                                                        \
    }

    STAGE_HL(sb + AT_V,  g_Qh, g_Ql, base + (size_t)nb * BLK * DH);
    STAGE_HL(sb + AT_K0, g_Kh, g_Kl, base + (size_t)blk_of(0, nb, rand_idx) * BLK * DH);
    cp_commit();
    cp_wait<0>();
    __syncthreads();

    uint32_t qh[4][4], ql[4][4];
#pragma unroll
    for (int ks = 0; ks < 4; ks++) {
        const int arow = 16 * w + r8 + ((tile & 1) << 3);
        const int aseg = ks * 2 + ((tile >> 1) & 1);
        const uint32_t aoff = (uint32_t)(arow * 128 + ((aseg ^ (arow & 7)) << 4));
        ldm_x4(qh[ks], sb + AT_V + aoff);
        ldm_x4(ql[ks], sb + AT_V + 8192 + aoff);
    }
    __syncthreads();

    STAGE_HL(sb + AT_V,  g_Vh, g_Vl, base + (size_t)blk_of(0, nb, rand_idx) * BLK * DH);
    cp_commit();
    STAGE_HL(sb + AT_K1, g_Kh, g_Kl, base + (size_t)blk_of(1, nb, rand_idx) * BLK * DH);
    cp_commit();

    float of[8][4];
#pragma unroll
    for (int i = 0; i < 8; i++)
#pragma unroll
        for (int jj = 0; jj < 4; jj++) of[i][jj] = 0.f;
    float mst0 = -1e30f, mst1 = -1e30f, lst0 = 0.f, lst1 = 0.f;

    for (int j = 0; j < MBL; j++) {
        const uint32_t kbuf = sb + ((j & 1) ? AT_K1 : AT_K0);

        float sf[8][4];
#pragma unroll
        for (int nf = 0; nf < 8; nf++)
#pragma unroll
            for (int r = 0; r < 4; r++) sf[nf][r] = 0.f;

#pragma unroll
        for (int ks = 0; ks < 4; ks++) {
            uint32_t kh[4][4], kl[4][4];
#pragma unroll
            for (int p = 0; p < 4; p++) {
                const int brow = 16 * p + r8 + ((tile >> 1) << 3);
                const int bseg = ks * 2 + (tile & 1);
                const uint32_t boff = (uint32_t)(brow * 128 + ((bseg ^ (brow & 7)) << 4));
                ldm_x4(kh[p], kbuf + boff);
                ldm_x4(kl[p], kbuf + 8192 + boff);
            }
#pragma unroll
            for (int nf = 0; nf < 8; nf++)
                mma_bf16(sf[nf], qh[ks], &kh[nf >> 1][(nf & 1) * 2]);
#pragma unroll
            for (int nf = 0; nf < 8; nf++)
                mma_bf16(sf[nf], qh[ks], &kl[nf >> 1][(nf & 1) * 2]);
#pragma unroll
            for (int nf = 0; nf < 8; nf++)
                mma_bf16(sf[nf], ql[ks], &kh[nf >> 1][(nf & 1) * 2]);
        }

        float rmax0 = sf[0][0], rmax1 = sf[0][2];
#pragma unroll
        for (int nf = 0; nf < 8; nf++) {
            rmax0 = fmaxf(rmax0, fmaxf(sf[nf][0], sf[nf][1]));
            rmax1 = fmaxf(rmax1, fmaxf(sf[nf][2], sf[nf][3]));
        }
        rmax0 = fmaxf(rmax0, __shfl_xor_sync(0xffffffffu, rmax0, 1));
        rmax0 = fmaxf(rmax0, __shfl_xor_sync(0xffffffffu, rmax0, 2));
        rmax1 = fmaxf(rmax1, __shfl_xor_sync(0xffffffffu, rmax1, 1));
        rmax1 = fmaxf(rmax1, __shfl_xor_sync(0xffffffffu, rmax1, 2));
        const float mn0 = fmaxf(mst0, rmax0);
        const float mn1 = fmaxf(mst1, rmax1);
        const float al0 = exp2f((mst0 - mn0) * CC);
        const float al1 = exp2f((mst1 - mn1) * CC);

        float rsum0 = 0.f, rsum1 = 0.f;
        uint32_t pah[4][4], pal[4][4];
#pragma unroll
        for (int t = 0; t < 4; t++) {
#pragma unroll
            for (int hl = 0; hl < 2; hl++) {
                int nf = 2 * t + hl;
                float p0 = exp2f((sf[nf][0] - mn0) * CC);
                float p1 = exp2f((sf[nf][1] - mn0) * CC);
                float p2 = exp2f((sf[nf][2] - mn1) * CC);
                float p3 = exp2f((sf[nf][3] - mn1) * CC);
                rsum0 += p0 + p1;
                rsum1 += p2 + p3;
                uint32_t h01 = pack_bf2(p0, p1);
                uint32_t h23 = pack_bf2(p2, p3);
                __nv_bfloat162 hv01 = *(__nv_bfloat162*)&h01;
                __nv_bfloat162 hv23 = *(__nv_bfloat162*)&h23;
                pah[t][2 * hl + 0] = h01;
                pah[t][2 * hl + 1] = h23;
                pal[t][2 * hl + 0] = pack_bf2(p0 - __bfloat162float(hv01.x),
                                              p1 - __bfloat162float(hv01.y));
                pal[t][2 * hl + 1] = pack_bf2(p2 - __bfloat162float(hv23.x),
                                              p3 - __bfloat162float(hv23.y));
            }
        }
        rsum0 += __shfl_xor_sync(0xffffffffu, rsum0, 1);
        rsum0 += __shfl_xor_sync(0xffffffffu, rsum0, 2);
        rsum1 += __shfl_xor_sync(0xffffffffu, rsum1, 1);
        rsum1 += __shfl_xor_sync(0xffffffffu, rsum1, 2);
        lst0 = lst0 * al0 + rsum0;
        lst1 = lst1 * al1 + rsum1;
        mst0 = mn0;
        mst1 = mn1;
#pragma unroll
        for (int nf = 0; nf < 8; nf++) {
            of[nf][0] *= al0; of[nf][1] *= al0;
            of[nf][2] *= al1; of[nf][3] *= al1;
        }

        if (j < MBL - 1) cp_wait<1>(); else cp_wait<0>();
        __syncthreads();

#pragma unroll
        for (int t = 0; t < 4; t++) {
            const int vkey = 16 * t + (lane & 7) + ((sel & 1) << 3);
#pragma unroll
            for (int g = 0; g < 4; g++) {
                const int vseg = 2 * g + (sel >> 1);
                const uint32_t voff = (uint32_t)(vkey * 128 + ((vseg ^ (vkey & 7)) << 4));
                uint32_t vh[4], vl[4];
                ldm_x4t(vh, sb + AT_V + voff);
                ldm_x4t(vl, sb + AT_V + 8192 + voff);
                mma_bf16(of[2 * g + 0], pah[t], &vh[0]);
                mma_bf16(of[2 * g + 1], pah[t], &vh[2]);
                mma_bf16(of[2 * g + 0], pal[t], &vh[0]);
                mma_bf16(of[2 * g + 1], pal[t], &vh[2]);
                mma_bf16(of[2 * g + 0], pah[t], &vl[0]);
                mma_bf16(of[2 * g + 1], pah[t], &vl[2]);
            }
        }

        if (j < MBL - 1) {
            cp_wait<0>();
            __syncthreads();
            size_t v_b = base + (size_t)blk_of(j + 1, nb, rand_idx) * BLK * DH;
            STAGE_HL(sb + AT_V, g_Vh, g_Vl, v_b);
            cp_commit();
            if (j < MBL - 2) {
                size_t k_b = base + (size_t)blk_of(j + 2, nb, rand_idx) * BLK * DH;
                STAGE_HL(sb + ((j & 1) ? AT_K1 : AT_K0), g_Kh, g_Kl, k_b);
                cp_commit();
            }
        }
    }

    // ---- epilogue: store normalized O as fp16 hi/lo (out-proj A operand) ----
    const int b = bh >> 3, h = bh & 7;
    const int r0 = 16 * w + qrow;
    const float inv0 = 1.f / lst0;
    const float inv1 = 1.f / lst1;
    __half* AOh = g_Inh + 3 * IN_STRIDE;
    __half* AOl = g_Inl + 3 * IN_STRIDE;
#pragma unroll
    for (int nf = 0; nf < 8; nf++) {
        int d = nf * 8 + qc;
        float v00 = of[nf][0] * inv0, v01 = of[nf][1] * inv0;
        float v10 = of[nf][2] * inv1, v11 = of[nf][3] * inv1;
        size_t a0 = (size_t)(b * SEQ + nb * BLK + r0) * EMB + h * DH + d;
        size_t a1 = (size_t)(b * SEQ + nb * BLK + r0 + 8) * EMB + h * DH + d;
        __half h00 = __float2half(v00), h01 = __float2half(v01);
        __half h10 = __float2half(v10), h11 = __float2half(v11);
        *(__half2*)&AOh[a0] = __halves2half2(h00, h01);
        *(__half2*)&AOh[a1] = __halves2half2(h10, h11);
        *(__half2*)&AOl[a0] = __halves2half2(
            __float2half(v00 - __half2float(h00)),
            __float2half(v01 - __half2float(h01)));
        *(__half2*)&AOl[a1] = __halves2half2(
            __float2half(v10 - __half2float(h10)),
            __float2half(v11 - __half2float(h11)));
    }
#undef STAGE_HL
}

// ============================================================
extern "C" void kernel_launch(void* const* d_in, const int* in_sizes, int n_in,
                              void* d_out, int out_size)
{
    const float* query   = (const float*)d_in[0];
    const float* key_inp = (const float*)d_in[1];
    const float* value   = (const float*)d_in[2];
    const float* q_w     = (const float*)d_in[3];
    const float* k_w     = (const float*)d_in[4];
    const float* v_w     = (const float*)d_in[5];
    const float* q_b     = (const float*)d_in[6];
    const float* k_b     = (const float*)d_in[7];
    const float* v_b     = (const float*)d_in[8];
    const float* out_w   = (const float*)d_in[9];
    const float* out_b   = (const float*)d_in[10];
    const int*   rand_idx= (const int*)d_in[11];
    float* out = (float*)d_out;

    static bool attr_set = false;
    if (!attr_set) {
        cudaFuncSetAttribute(gemm_mma,
                             cudaFuncAttributeMaxDynamicSharedMemorySize, GS_SMEM);
        attr_set = true;
    }

    conv_all<<<8192, 256>>>(q_w, k_w, v_w, out_w, query, key_inp, value);

    dim3 gQKV(128, 12);
    gemm_mma<<<gQKV, 256, GS_SMEM>>>(q_b, k_b, v_b, out_b, out, 0);

    dim3 gAttn(NBLK, BATCH * NH);
    attn_mma<<<gAttn, 128>>>(rand_idx);

    dim3 gOut(128, 4);
    gemm_mma<<<gOut, 256, GS_SMEM>>>(q_b, k_b, v_b, out_b, out, 3);
}

// round 13
// speedup vs baseline: 1.8553x; 1.0562x over previous
#include <cuda_runtime.h>
#include <cuda_bf16.h>
#include <cuda_fp16.h>
#include <math.h>
#include <cstdint>

#define SEQ   8192
#define BATCH 2
#define EMB   512
#define NH    8
#define DH    64
#define NBLK  128      // SEQ / 64
#define BLK   64
#define MBL   8        // gathered blocks per query block
#define NGLOB 2
#define NWIN  3

#define IN_STRIDE ((size_t)16384 * 512)

// ---- device-global scratch (allocation-free) ----
// A-side activations, fp16 hi/lo: slots 0=q_in 1=k_in 2=v_in 3=attn_out
__device__ __half g_Inh[4 * IN_STRIDE];
__device__ __half g_Inl[4 * IN_STRIDE];
// Q/K/V (post-projection) bf16 hi/lo, [b][h][s][d]  (attention path)
__device__ __nv_bfloat16 g_Qh[(size_t)BATCH * NH * SEQ * DH];
__device__ __nv_bfloat16 g_Ql[(size_t)BATCH * NH * SEQ * DH];
__device__ __nv_bfloat16 g_Kh[(size_t)BATCH * NH * SEQ * DH];
__device__ __nv_bfloat16 g_Kl[(size_t)BATCH * NH * SEQ * DH];
__device__ __nv_bfloat16 g_Vh[(size_t)BATCH * NH * SEQ * DH];
__device__ __nv_bfloat16 g_Vl[(size_t)BATCH * NH * SEQ * DH];
// fp16 single weights: [mat][n][k], mat: 0=q 1=k 2=v 3=out
__device__ __half g_Wh[4u * 512u * 512u];

// ============================================================
// helpers (baseline PTX only)
// ============================================================
__device__ __forceinline__ uint32_t smem_u32(const void* p) {
    uint32_t a;
    asm("{ .reg .u64 t; cvta.to.shared.u64 t, %1; cvt.u32.u64 %0, t; }"
        : "=r"(a) : "l"(p));
    return a;
}
__device__ __forceinline__ void ldm_x4(uint32_t* r, uint32_t addr) {
    asm volatile("ldmatrix.sync.aligned.m8n8.x4.shared.b16 {%0,%1,%2,%3}, [%4];"
                 : "=r"(r[0]), "=r"(r[1]), "=r"(r[2]), "=r"(r[3]) : "r"(addr));
}
__device__ __forceinline__ void ldm_x4t(uint32_t* r, uint32_t addr) {
    asm volatile("ldmatrix.sync.aligned.m8n8.x4.trans.shared.b16 {%0,%1,%2,%3}, [%4];"
                 : "=r"(r[0]), "=r"(r[1]), "=r"(r[2]), "=r"(r[3]) : "r"(addr));
}
__device__ __forceinline__ void mma_bf16(float* d, const uint32_t* a, const uint32_t* b) {
    asm volatile(
        "mma.sync.aligned.m16n8k16.row.col.f32.bf16.bf16.f32 "
        "{%0,%1,%2,%3}, {%4,%5,%6,%7}, {%8,%9}, {%0,%1,%2,%3};"
        : "+f"(d[0]), "+f"(d[1]), "+f"(d[2]), "+f"(d[3])
        : "r"(a[0]), "r"(a[1]), "r"(a[2]), "r"(a[3]), "r"(b[0]), "r"(b[1]));
}
__device__ __forceinline__ void mma_fp16(float* d, const uint32_t* a, const uint32_t* b) {
    asm volatile(
        "mma.sync.aligned.m16n8k16.row.col.f32.f16.f16.f32 "
        "{%0,%1,%2,%3}, {%4,%5,%6,%7}, {%8,%9}, {%0,%1,%2,%3};"
        : "+f"(d[0]), "+f"(d[1]), "+f"(d[2]), "+f"(d[3])
        : "r"(a[0]), "r"(a[1]), "r"(a[2]), "r"(a[3]), "r"(b[0]), "r"(b[1]));
}
__device__ __forceinline__ void cp16(uint32_t dst, const void* src) {
    asm volatile("cp.async.cg.shared.global [%0], [%1], 16;" :: "r"(dst), "l"(src) : "memory");
}
__device__ __forceinline__ void cp_commit() {
    asm volatile("cp.async.commit_group;" ::: "memory");
}
template<int N> __device__ __forceinline__ void cp_wait() {
    asm volatile("cp.async.wait_group %0;" :: "n"(N) : "memory");
}
__device__ __forceinline__ uint32_t pack_bf2(float x, float y) {
    __nv_bfloat162 v = __halves2bfloat162(__float2bfloat16(x), __float2bfloat16(y));
    return *(uint32_t*)&v;
}

// ============================================================
// Fused conversion: weights (fp32 -> single fp16, [mat][n][k]) +
// inputs (fp32 -> fp16 hi/lo).
// ============================================================
__global__ void conv_all(const float* __restrict__ qw, const float* __restrict__ kw,
                         const float* __restrict__ vw, const float* __restrict__ ow,
                         const float* __restrict__ qi, const float* __restrict__ ki,
                         const float* __restrict__ vi)
{
    const int bx = blockIdx.x;
    if (bx < 2048) {
        const int mat = bx >> 9;
        const int n   = bx & 511;
        const float* src = (mat == 0) ? qw : (mat == 1) ? kw : (mat == 2) ? vw : ow;
        for (int k = threadIdx.x; k < 512; k += 256) {
            float v;
            if (mat < 3) v = src[((size_t)(n >> 6) * 512 + k) * 64 + (n & 63)];
            else         v = src[(size_t)n * 512 + k];
            g_Wh[(size_t)mat * 262144 + (size_t)n * 512 + k] = __float2half(v);
        }
    } else {
        const int bi  = bx - 2048;
        const int mat = bi >> 11;
        const int blk = bi & 2047;
        const float* src = (mat == 0) ? qi : (mat == 1) ? ki : vi;
        __half* dh = g_Inh + (size_t)mat * IN_STRIDE;
        __half* dl = g_Inl + (size_t)mat * IN_STRIDE;
#pragma unroll
        for (int i = 0; i < 4; i++) {
            size_t o4 = (size_t)blk * 1024 + i * 256 + threadIdx.x;
            float4 x = *(const float4*)&src[o4 * 4];
            __half h0 = __float2half(x.x), h1 = __float2half(x.y);
            __half h2 = __float2half(x.z), h3 = __float2half(x.w);
            __half l0 = __float2half(x.x - __half2float(h0));
            __half l1 = __float2half(x.y - __half2float(h1));
            __half l2 = __float2half(x.z - __half2float(h2));
            __half l3 = __float2half(x.w - __half2float(h3));
            *(__half2*)&dh[o4 * 4 + 0] = __halves2half2(h0, h1);
            *(__half2*)&dh[o4 * 4 + 2] = __halves2half2(h2, h3);
            *(__half2*)&dl[o4 * 4 + 0] = __halves2half2(l0, l1);
            *(__half2*)&dl[o4 * 4 + 2] = __halves2half2(l2, l3);
        }
    }
}

// ============================================================
// HMMA GEMM v3: fp16 2-term, CTA 128x64, 128 thr (4 warps, 2x2 of 64x32).
// 4-warp barriers + 4 CTAs/SM (attention-like structure).
// 2-stage cp.async pipeline; stage = Ah 8K | Al 8K | B 4K = 20KB.
// Grid (128, 8*nmats): mode = base + by>>3, n0 = (by&7)*64.
// ============================================================
#define GS_STAGE 20480
#define GS_SMEM  (2 * GS_STAGE)   // 40 KB

__global__ __launch_bounds__(128, 4)
void gemm_mma(const float* __restrict__ qb, const float* __restrict__ kb,
              const float* __restrict__ vb, const float* __restrict__ ob,
              float* __restrict__ Cout, int mode_base)
{
    extern __shared__ char gsm[];
    const uint32_t sb = smem_u32(gsm);
    const int tid  = threadIdx.x;
    const int wid  = tid >> 5;
    const int lane = tid & 31;
    const int wm   = wid >> 1;          // 0..1 (64 rows)
    const int wn   = wid & 1;           // 0..1 (32 cols)
    const int m0   = blockIdx.x * 128;
    const int mode = mode_base + (blockIdx.y >> 3);
    const int n0   = (blockIdx.y & 7) * 64;

    const __half* __restrict__ Ah = g_Inh + (size_t)mode * IN_STRIDE;
    const __half* __restrict__ Al = g_Inl + (size_t)mode * IN_STRIDE;
    const __half* __restrict__ Bw = g_Wh  + (size_t)mode * 262144;
    const float* __restrict__ bias = (mode == 0) ? qb : (mode == 1) ? kb
                                   : (mode == 2) ? vb : ob;

    // stage layout: Ah 0-8K, Al 8-16K, B 16-20K (64B rows, swizzled)
#define GPREFETCH(K0, ST)                                                        \
    {                                                                            \
        uint32_t d0 = sb + (ST) * GS_STAGE;                                      \
        _Pragma("unroll")                                                        \
        for (int i = 0; i < 8; i++) {                                            \
            int idx = tid + 128 * i;          /* 0..1023: A hi/lo */             \
            int mt  = idx >> 9;                                                  \
            int row = (idx >> 2) & 127;                                          \
            int seg = idx & 3;                                                   \
            const __half* src = (mt ? Al : Ah)                                   \
                + (size_t)(m0 + row) * 512 + (K0) + seg * 8;                     \
            cp16(d0 + mt * 8192 + row * 64 + ((seg ^ ((row >> 1) & 3)) << 4),    \
                 src);                                                           \
        }                                                                        \
        _Pragma("unroll")                                                        \
        for (int i = 0; i < 2; i++) {                                            \
            int r2  = tid + 128 * i;          /* 0..255: B */                    \
            int row = r2 >> 2;                /* 0..63 */                        \
            int seg = r2 & 3;                                                    \
            const __half* src = Bw + (size_t)(n0 + row) * 512 + (K0) + seg * 8;  \
            cp16(d0 + 16384 + row * 64 + ((seg ^ ((row >> 1) & 3)) << 4), src);  \
        }                                                                        \
    }

    GPREFETCH(0, 0);
    cp_commit();

    float acc[4][4][4];
#pragma unroll
    for (int i = 0; i < 4; i++)
#pragma unroll
        for (int j = 0; j < 4; j++)
#pragma unroll
            for (int r = 0; r < 4; r++) acc[i][j][r] = 0.f;

    const int tile = lane >> 3;
    const int r8   = lane & 7;

    for (int it = 0; it < 16; it++) {
        cp_wait<0>();
        __syncthreads();
        if (it + 1 < 16) {
            GPREFETCH((it + 1) * 32, (it + 1) & 1);
            cp_commit();
        }
        const uint32_t stg  = sb + (it & 1) * GS_STAGE;
        const uint32_t aAhi = stg;
        const uint32_t aAlo = stg + 8192;
        const uint32_t aB   = stg + 16384;

#pragma unroll
        for (int ks = 0; ks < 2; ks++) {
            const int k16 = ks * 16;
            const int arow_off = r8 + ((tile & 1) << 3);
            const int aseg = (k16 + ((tile >= 2) ? 8 : 0)) >> 3;
            const int brow_off = r8 + ((tile >> 1) << 3);
            const int bseg = (k16 + ((tile & 1) ? 8 : 0)) >> 3;

            uint32_t ah[4][4], al[4][4], bf[2][4];
#pragma unroll
            for (int mi = 0; mi < 4; mi++) {
                int row = wm * 64 + mi * 16 + arow_off;
                uint32_t off = (uint32_t)(row * 64 + ((aseg ^ ((row >> 1) & 3)) << 4));
                ldm_x4(ah[mi], aAhi + off);
                ldm_x4(al[mi], aAlo + off);
            }
#pragma unroll
            for (int p = 0; p < 2; p++) {
                int row = wn * 32 + p * 16 + brow_off;
                uint32_t off = (uint32_t)(row * 64 + ((bseg ^ ((row >> 1) & 3)) << 4));
                ldm_x4(bf[p], aB + off);
            }

#pragma unroll
            for (int mi = 0; mi < 4; mi++)
#pragma unroll
                for (int ni = 0; ni < 4; ni++)
                    mma_fp16(acc[mi][ni], ah[mi], &bf[ni >> 1][(ni & 1) * 2]);
#pragma unroll
            for (int mi = 0; mi < 4; mi++)
#pragma unroll
                for (int ni = 0; ni < 4; ni++)
                    mma_fp16(acc[mi][ni], al[mi], &bf[ni >> 1][(ni & 1) * 2]);
        }
    }

    const int mrb = m0 + wm * 64;
    const int ncb = n0 + wn * 32;
#pragma unroll
    for (int mi = 0; mi < 4; mi++) {
#pragma unroll
        for (int ni = 0; ni < 4; ni++) {
            int n = ncb + ni * 8 + (lane & 3) * 2;
            float2 bv = *(const float2*)&bias[n];
#pragma unroll
            for (int hf = 0; hf < 2; hf++) {
                int m = mrb + mi * 16 + (lane >> 2) + hf * 8;
                float c0 = acc[mi][ni][hf * 2 + 0] + bv.x;
                float c1 = acc[mi][ni][hf * 2 + 1] + bv.y;
                if (mode < 3) {
                    int bb = m & 1, s = m >> 1;
                    int hh = n >> 6, d = n & 63;
                    size_t addr = (((size_t)bb * NH + hh) * SEQ + s) * DH + d;
                    __nv_bfloat16 h0 = __float2bfloat16(c0);
                    __nv_bfloat16 h1 = __float2bfloat16(c1);
                    __nv_bfloat16 e0 = __float2bfloat16(c0 - __bfloat162float(h0));
                    __nv_bfloat16 e1 = __float2bfloat16(c1 - __bfloat162float(h1));
                    __nv_bfloat16* Ch = (mode == 0) ? g_Qh : (mode == 1) ? g_Kh : g_Vh;
                    __nv_bfloat16* Cl = (mode == 0) ? g_Ql : (mode == 1) ? g_Kl : g_Vl;
                    *(__nv_bfloat162*)&Ch[addr] = __halves2bfloat162(h0, h1);
                    *(__nv_bfloat162*)&Cl[addr] = __halves2bfloat162(e0, e1);
                } else {
                    int bb = m >> 13, s = m & (SEQ - 1);
                    *(float2*)&Cout[(size_t)(s * BATCH + bb) * EMB + n] = make_float2(c0, c1);
                }
            }
        }
    }
#undef GPREFETCH
}

// ============================================================
// Attention v3 (R12-proven, bf16 3-term): 128 threads, 4 warps;
// warp = 16 q-rows x 64 keys. Epilogue writes AO as fp16 hi/lo.
// ============================================================
#define AT_K0 0
#define AT_K1 16384
#define AT_V  32768

__device__ __forceinline__ int blk_of(int j, int nb, const int* __restrict__ ri) {
    if (j < NGLOB) return j;
    if (j < NGLOB + NWIN) return (nb + j - 3 + NBLK) & (NBLK - 1);
    return ri[nb * 3 + (j - 5)];
}

__global__ __launch_bounds__(128, 3)
void attn_mma(const int* __restrict__ rand_idx)
{
    __shared__ char smb[49152];
    const uint32_t sb = smem_u32(smb);

    const int nb  = blockIdx.x;
    const int bh  = blockIdx.y;
    const int tid = threadIdx.x;
    const int w    = tid >> 5;
    const int lane = tid & 31;
    const int tile = lane >> 3;
    const int r8   = lane & 7;
    const int sel  = lane >> 3;
    const int qrow = lane >> 2;
    const int qc   = (lane & 3) * 2;
    const size_t base = (size_t)bh * SEQ * DH;
    const float CC = 0.18033688011112042f;

#define STAGE_HL(DST, SRCH, SRCL, ROWBASE)                                       \
    {                                                                            \
        _Pragma("unroll")                                                        \
        for (int i = 0; i < 8; i++) {                                            \
            int idx = tid + 128 * i;                                             \
            int mh  = idx >> 9;                                                  \
            int row = (idx >> 3) & 63;                                           \
            int seg = idx & 7;                                                   \
            const __nv_bfloat16* src = (mh ? (SRCL) : (SRCH)) + (ROWBASE)        \
                                       + (size_t)row * 64 + seg * 8;             \
            cp16((DST) + mh * 8192 + row * 128 + ((seg ^ (row & 7)) << 4), src); \
        }                                                                        \
    }

    STAGE_HL(sb + AT_V,  g_Qh, g_Ql, base + (size_t)nb * BLK * DH);
    STAGE_HL(sb + AT_K0, g_Kh, g_Kl, base + (size_t)blk_of(0, nb, rand_idx) * BLK * DH);
    cp_commit();
    cp_wait<0>();
    __syncthreads();

    uint32_t qh[4][4], ql[4][4];
#pragma unroll
    for (int ks = 0; ks < 4; ks++) {
        const int arow = 16 * w + r8 + ((tile & 1) << 3);
        const int aseg = ks * 2 + ((tile >> 1) & 1);
        const uint32_t aoff = (uint32_t)(arow * 128 + ((aseg ^ (arow & 7)) << 4));
        ldm_x4(qh[ks], sb + AT_V + aoff);
        ldm_x4(ql[ks], sb + AT_V + 8192 + aoff);
    }
    __syncthreads();

    STAGE_HL(sb + AT_V,  g_Vh, g_Vl, base + (size_t)blk_of(0, nb, rand_idx) * BLK * DH);
    cp_commit();
    STAGE_HL(sb + AT_K1, g_Kh, g_Kl, base + (size_t)blk_of(1, nb, rand_idx) * BLK * DH);
    cp_commit();

    float of[8][4];
#pragma unroll
    for (int i = 0; i < 8; i++)
#pragma unroll
        for (int jj = 0; jj < 4; jj++) of[i][jj] = 0.f;
    float mst0 = -1e30f, mst1 = -1e30f, lst0 = 0.f, lst1 = 0.f;

    for (int j = 0; j < MBL; j++) {
        const uint32_t kbuf = sb + ((j & 1) ? AT_K1 : AT_K0);

        float sf[8][4];
#pragma unroll
        for (int nf = 0; nf < 8; nf++)
#pragma unroll
            for (int r = 0; r < 4; r++) sf[nf][r] = 0.f;

#pragma unroll
        for (int ks = 0; ks < 4; ks++) {
            uint32_t kh[4][4], kl[4][4];
#pragma unroll
            for (int p = 0; p < 4; p++) {
                const int brow = 16 * p + r8 + ((tile >> 1) << 3);
                const int bseg = ks * 2 + (tile & 1);
                const uint32_t boff = (uint32_t)(brow * 128 + ((bseg ^ (brow & 7)) << 4));
                ldm_x4(kh[p], kbuf + boff);
                ldm_x4(kl[p], kbuf + 8192 + boff);
            }
#pragma unroll
            for (int nf = 0; nf < 8; nf++)
                mma_bf16(sf[nf], qh[ks], &kh[nf >> 1][(nf & 1) * 2]);
#pragma unroll
            for (int nf = 0; nf < 8; nf++)
                mma_bf16(sf[nf], qh[ks], &kl[nf >> 1][(nf & 1) * 2]);
#pragma unroll
            for (int nf = 0; nf < 8; nf++)
                mma_bf16(sf[nf], ql[ks], &kh[nf >> 1][(nf & 1) * 2]);
        }

        float rmax0 = sf[0][0], rmax1 = sf[0][2];
#pragma unroll
        for (int nf = 0; nf < 8; nf++) {
            rmax0 = fmaxf(rmax0, fmaxf(sf[nf][0], sf[nf][1]));
            rmax1 = fmaxf(rmax1, fmaxf(sf[nf][2], sf[nf][3]));
        }
        rmax0 = fmaxf(rmax0, __shfl_xor_sync(0xffffffffu, rmax0, 1));
        rmax0 = fmaxf(rmax0, __shfl_xor_sync(0xffffffffu, rmax0, 2));
        rmax1 = fmaxf(rmax1, __shfl_xor_sync(0xffffffffu, rmax1, 1));
        rmax1 = fmaxf(rmax1, __shfl_xor_sync(0xffffffffu, rmax1, 2));
        const float mn0 = fmaxf(mst0, rmax0);
        const float mn1 = fmaxf(mst1, rmax1);
        const float al0 = exp2f((mst0 - mn0) * CC);
        const float al1 = exp2f((mst1 - mn1) * CC);

        float rsum0 = 0.f, rsum1 = 0.f;
        uint32_t pah[4][4], pal[4][4];
#pragma unroll
        for (int t = 0; t < 4; t++) {
#pragma unroll
            for (int hl = 0; hl < 2; hl++) {
                int nf = 2 * t + hl;
                float p0 = exp2f((sf[nf][0] - mn0) * CC);
                float p1 = exp2f((sf[nf][1] - mn0) * CC);
                float p2 = exp2f((sf[nf][2] - mn1) * CC);
                float p3 = exp2f((sf[nf][3] - mn1) * CC);
                rsum0 += p0 + p1;
                rsum1 += p2 + p3;
                uint32_t h01 = pack_bf2(p0, p1);
                uint32_t h23 = pack_bf2(p2, p3);
                __nv_bfloat162 hv01 = *(__nv_bfloat162*)&h01;
                __nv_bfloat162 hv23 = *(__nv_bfloat162*)&h23;
                pah[t][2 * hl + 0] = h01;
                pah[t][2 * hl + 1] = h23;
                pal[t][2 * hl + 0] = pack_bf2(p0 - __bfloat162float(hv01.x),
                                              p1 - __bfloat162float(hv01.y));
                pal[t][2 * hl + 1] = pack_bf2(p2 - __bfloat162float(hv23.x),
                                              p3 - __bfloat162float(hv23.y));
            }
        }
        rsum0 += __shfl_xor_sync(0xffffffffu, rsum0, 1);
        rsum0 += __shfl_xor_sync(0xffffffffu, rsum0, 2);
        rsum1 += __shfl_xor_sync(0xffffffffu, rsum1, 1);
        rsum1 += __shfl_xor_sync(0xffffffffu, rsum1, 2);
        lst0 = lst0 * al0 + rsum0;
        lst1 = lst1 * al1 + rsum1;
        mst0 = mn0;
        mst1 = mn1;
#pragma unroll
        for (int nf = 0; nf < 8; nf++) {
            of[nf][0] *= al0; of[nf][1] *= al0;
            of[nf][2] *= al1; of[nf][3] *= al1;
        }

        if (j < MBL - 1) cp_wait<1>(); else cp_wait<0>();
        __syncthreads();

#pragma unroll
        for (int t = 0; t < 4; t++) {
            const int vkey = 16 * t + (lane & 7) + ((sel & 1) << 3);
#pragma unroll
            for (int g = 0; g < 4; g++) {
                const int vseg = 2 * g + (sel >> 1);
                const uint32_t voff = (uint32_t)(vkey * 128 + ((vseg ^ (vkey & 7)) << 4));
                uint32_t vh[4], vl[4];
                ldm_x4t(vh, sb + AT_V + voff);
                ldm_x4t(vl, sb + AT_V + 8192 + voff);
                mma_bf16(of[2 * g + 0], pah[t], &vh[0]);
                mma_bf16(of[2 * g + 1], pah[t], &vh[2]);
                mma_bf16(of[2 * g + 0], pal[t], &vh[0]);
                mma_bf16(of[2 * g + 1], pal[t], &vh[2]);
                mma_bf16(of[2 * g + 0], pah[t], &vl[0]);
                mma_bf16(of[2 * g + 1], pah[t], &vl[2]);
            }
        }

        if (j < MBL - 1) {
            cp_wait<0>();
            __syncthreads();
            size_t v_b = base + (size_t)blk_of(j + 1, nb, rand_idx) * BLK * DH;
            STAGE_HL(sb + AT_V, g_Vh, g_Vl, v_b);
            cp_commit();
            if (j < MBL - 2) {
                size_t k_b = base + (size_t)blk_of(j + 2, nb, rand_idx) * BLK * DH;
                STAGE_HL(sb + ((j & 1) ? AT_K1 : AT_K0), g_Kh, g_Kl, k_b);
                cp_commit();
            }
        }
    }

    // ---- epilogue: store normalized O as fp16 hi/lo (out-proj A operand) ----
    const int b = bh >> 3, h = bh & 7;
    const int r0 = 16 * w + qrow;
    const float inv0 = 1.f / lst0;
    const float inv1 = 1.f / lst1;
    __half* AOh = g_Inh + 3 * IN_STRIDE;
    __half* AOl = g_Inl + 3 * IN_STRIDE;
#pragma unroll
    for (int nf = 0; nf < 8; nf++) {
        int d = nf * 8 + qc;
        float v00 = of[nf][0] * inv0, v01 = of[nf][1] * inv0;
        float v10 = of[nf][2] * inv1, v11 = of[nf][3] * inv1;
        size_t a0 = (size_t)(b * SEQ + nb * BLK + r0) * EMB + h * DH + d;
        size_t a1 = (size_t)(b * SEQ + nb * BLK + r0 + 8) * EMB + h * DH + d;
        __half h00 = __float2half(v00), h01 = __float2half(v01);
        __half h10 = __float2half(v10), h11 = __float2half(v11);
        *(__half2*)&AOh[a0] = __halves2half2(h00, h01);
        *(__half2*)&AOh[a1] = __halves2half2(h10, h11);
        *(__half2*)&AOl[a0] = __halves2half2(
            __float2half(v00 - __half2float(h00)),
            __float2half(v01 - __half2float(h01)));
        *(__half2*)&AOl[a1] = __halves2half2(
            __float2half(v10 - __half2float(h10)),
            __float2half(v11 - __half2float(h11)));
    }
#undef STAGE_HL
}

// ============================================================
extern "C" void kernel_launch(void* const* d_in, const int* in_sizes, int n_in,
                              void* d_out, int out_size)
{
    const float* query   = (const float*)d_in[0];
    const float* key_inp = (const float*)d_in[1];
    const float* value   = (const float*)d_in[2];
    const float* q_w     = (const float*)d_in[3];
    const float* k_w     = (const float*)d_in[4];
    const float* v_w     = (const float*)d_in[5];
    const float* q_b     = (const float*)d_in[6];
    const float* k_b     = (const float*)d_in[7];
    const float* v_b     = (const float*)d_in[8];
    const float* out_w   = (const float*)d_in[9];
    const float* out_b   = (const float*)d_in[10];
    const int*   rand_idx= (const int*)d_in[11];
    float* out = (float*)d_out;

    static bool attr_set = false;
    if (!attr_set) {
        cudaFuncSetAttribute(gemm_mma,
                             cudaFuncAttributeMaxDynamicSharedMemorySize, GS_SMEM);
        attr_set = true;
    }

    conv_all<<<8192, 256>>>(q_w, k_w, v_w, out_w, query, key_inp, value);

    dim3 gQKV(128, 24);
    gemm_mma<<<gQKV, 128, GS_SMEM>>>(q_b, k_b, v_b, out_b, out, 0);

    dim3 gAttn(NBLK, BATCH * NH);
    attn_mma<<<gAttn, 128>>>(rand_idx);

    dim3 gOut(128, 8);
    gemm_mma<<<gOut, 128, GS_SMEM>>>(q_b, k_b, v_b, out_b, out, 3);
}

// round 14
// speedup vs baseline: 2.0860x; 1.1243x over previous
#include <cuda_runtime.h>
#include <cuda_bf16.h>
#include <cuda_fp16.h>
#include <math.h>
#include <cstdint>

#define SEQ   8192
#define BATCH 2
#define EMB   512
#define NH    8
#define DH    64
#define NBLK  128      // SEQ / 64
#define BLK   64
#define MBL   8        // gathered blocks per query block
#define NGLOB 2
#define NWIN  3

#define IN_STRIDE ((size_t)16384 * 512)

// ---- device-global scratch (allocation-free) ----
// A-side activations, fp16 hi/lo: slots 0=q_in 1=k_in 2=v_in 3=attn_out
__device__ __half g_Inh[4 * IN_STRIDE];
__device__ __half g_Inl[4 * IN_STRIDE];
// post-projection: Q fp16 hi/lo; K,V single fp16. [b][h][s][d]
__device__ __half g_Qh[(size_t)BATCH * NH * SEQ * DH];
__device__ __half g_Ql[(size_t)BATCH * NH * SEQ * DH];
__device__ __half g_Ks[(size_t)BATCH * NH * SEQ * DH];
__device__ __half g_Vs[(size_t)BATCH * NH * SEQ * DH];
// fp16 single weights: [mat][n][k], mat: 0=q 1=k 2=v 3=out
__device__ __half g_Wh[4u * 512u * 512u];

// ============================================================
// helpers (baseline PTX only)
// ============================================================
__device__ __forceinline__ uint32_t smem_u32(const void* p) {
    uint32_t a;
    asm("{ .reg .u64 t; cvta.to.shared.u64 t, %1; cvt.u32.u64 %0, t; }"
        : "=r"(a) : "l"(p));
    return a;
}
__device__ __forceinline__ void ldm_x4(uint32_t* r, uint32_t addr) {
    asm volatile("ldmatrix.sync.aligned.m8n8.x4.shared.b16 {%0,%1,%2,%3}, [%4];"
                 : "=r"(r[0]), "=r"(r[1]), "=r"(r[2]), "=r"(r[3]) : "r"(addr));
}
__device__ __forceinline__ void ldm_x4t(uint32_t* r, uint32_t addr) {
    asm volatile("ldmatrix.sync.aligned.m8n8.x4.trans.shared.b16 {%0,%1,%2,%3}, [%4];"
                 : "=r"(r[0]), "=r"(r[1]), "=r"(r[2]), "=r"(r[3]) : "r"(addr));
}
__device__ __forceinline__ void mma_fp16(float* d, const uint32_t* a, const uint32_t* b) {
    asm volatile(
        "mma.sync.aligned.m16n8k16.row.col.f32.f16.f16.f32 "
        "{%0,%1,%2,%3}, {%4,%5,%6,%7}, {%8,%9}, {%0,%1,%2,%3};"
        : "+f"(d[0]), "+f"(d[1]), "+f"(d[2]), "+f"(d[3])
        : "r"(a[0]), "r"(a[1]), "r"(a[2]), "r"(a[3]), "r"(b[0]), "r"(b[1]));
}
__device__ __forceinline__ void cp16(uint32_t dst, const void* src) {
    asm volatile("cp.async.cg.shared.global [%0], [%1], 16;" :: "r"(dst), "l"(src) : "memory");
}
__device__ __forceinline__ void cp_commit() {
    asm volatile("cp.async.commit_group;" ::: "memory");
}
template<int N> __device__ __forceinline__ void cp_wait() {
    asm volatile("cp.async.wait_group %0;" :: "n"(N) : "memory");
}
__device__ __forceinline__ uint32_t pack_hf2(float x, float y) {
    __half2 v = __halves2half2(__float2half(x), __float2half(y));
    return *(uint32_t*)&v;
}

// ============================================================
// Fused conversion: weights (fp32 -> single fp16, [mat][n][k]) +
// inputs (fp32 -> fp16 hi/lo).
// ============================================================
__global__ void conv_all(const float* __restrict__ qw, const float* __restrict__ kw,
                         const float* __restrict__ vw, const float* __restrict__ ow,
                         const float* __restrict__ qi, const float* __restrict__ ki,
                         const float* __restrict__ vi)
{
    const int bx = blockIdx.x;
    if (bx < 2048) {
        const int mat = bx >> 9;
        const int n   = bx & 511;
        const float* src = (mat == 0) ? qw : (mat == 1) ? kw : (mat == 2) ? vw : ow;
        for (int k = threadIdx.x; k < 512; k += 256) {
            float v;
            if (mat < 3) v = src[((size_t)(n >> 6) * 512 + k) * 64 + (n & 63)];
            else         v = src[(size_t)n * 512 + k];
            g_Wh[(size_t)mat * 262144 + (size_t)n * 512 + k] = __float2half(v);
        }
    } else {
        const int bi  = bx - 2048;
        const int mat = bi >> 11;
        const int blk = bi & 2047;
        const float* src = (mat == 0) ? qi : (mat == 1) ? ki : vi;
        __half* dh = g_Inh + (size_t)mat * IN_STRIDE;
        __half* dl = g_Inl + (size_t)mat * IN_STRIDE;
#pragma unroll
        for (int i = 0; i < 4; i++) {
            size_t o4 = (size_t)blk * 1024 + i * 256 + threadIdx.x;
            float4 x = *(const float4*)&src[o4 * 4];
            __half h0 = __float2half(x.x), h1 = __float2half(x.y);
            __half h2 = __float2half(x.z), h3 = __float2half(x.w);
            __half l0 = __float2half(x.x - __half2float(h0));
            __half l1 = __float2half(x.y - __half2float(h1));
            __half l2 = __float2half(x.z - __half2float(h2));
            __half l3 = __float2half(x.w - __half2float(h3));
            *(__half2*)&dh[o4 * 4 + 0] = __halves2half2(h0, h1);
            *(__half2*)&dh[o4 * 4 + 2] = __halves2half2(h2, h3);
            *(__half2*)&dl[o4 * 4 + 0] = __halves2half2(l0, l1);
            *(__half2*)&dl[o4 * 4 + 2] = __halves2half2(l2, l3);
        }
    }
}

// ============================================================
// HMMA GEMM v3 (R13-proven): fp16 2-term, CTA 128x64, 128 thr, 4 CTAs/SM.
// Epilogue: mode0 -> Q fp16 hi/lo; mode1 -> K single; mode2 -> V single;
// mode3 -> fp32 out.
// ============================================================
#define GS_STAGE 20480
#define GS_SMEM  (2 * GS_STAGE)   // 40 KB

__global__ __launch_bounds__(128, 4)
void gemm_mma(const float* __restrict__ qb, const float* __restrict__ kb,
              const float* __restrict__ vb, const float* __restrict__ ob,
              float* __restrict__ Cout, int mode_base)
{
    extern __shared__ char gsm[];
    const uint32_t sb = smem_u32(gsm);
    const int tid  = threadIdx.x;
    const int wid  = tid >> 5;
    const int lane = tid & 31;
    const int wm   = wid >> 1;
    const int wn   = wid & 1;
    const int m0   = blockIdx.x * 128;
    const int mode = mode_base + (blockIdx.y >> 3);
    const int n0   = (blockIdx.y & 7) * 64;

    const __half* __restrict__ Ah = g_Inh + (size_t)mode * IN_STRIDE;
    const __half* __restrict__ Al = g_Inl + (size_t)mode * IN_STRIDE;
    const __half* __restrict__ Bw = g_Wh  + (size_t)mode * 262144;
    const float* __restrict__ bias = (mode == 0) ? qb : (mode == 1) ? kb
                                   : (mode == 2) ? vb : ob;

#define GPREFETCH(K0, ST)                                                        \
    {                                                                            \
        uint32_t d0 = sb + (ST) * GS_STAGE;                                      \
        _Pragma("unroll")                                                        \
        for (int i = 0; i < 8; i++) {                                            \
            int idx = tid + 128 * i;                                             \
            int mt  = idx >> 9;                                                  \
            int row = (idx >> 2) & 127;                                          \
            int seg = idx & 3;                                                   \
            const __half* src = (mt ? Al : Ah)                                   \
                + (size_t)(m0 + row) * 512 + (K0) + seg * 8;                     \
            cp16(d0 + mt * 8192 + row * 64 + ((seg ^ ((row >> 1) & 3)) << 4),    \
                 src);                                                           \
        }                                                                        \
        _Pragma("unroll")                                                        \
        for (int i = 0; i < 2; i++) {                                            \
            int r2  = tid + 128 * i;                                             \
            int row = r2 >> 2;                                                   \
            int seg = r2 & 3;                                                    \
            const __half* src = Bw + (size_t)(n0 + row) * 512 + (K0) + seg * 8;  \
            cp16(d0 + 16384 + row * 64 + ((seg ^ ((row >> 1) & 3)) << 4), src);  \
        }                                                                        \
    }

    GPREFETCH(0, 0);
    cp_commit();

    float acc[4][4][4];
#pragma unroll
    for (int i = 0; i < 4; i++)
#pragma unroll
        for (int j = 0; j < 4; j++)
#pragma unroll
            for (int r = 0; r < 4; r++) acc[i][j][r] = 0.f;

    const int tile = lane >> 3;
    const int r8   = lane & 7;

    for (int it = 0; it < 16; it++) {
        cp_wait<0>();
        __syncthreads();
        if (it + 1 < 16) {
            GPREFETCH((it + 1) * 32, (it + 1) & 1);
            cp_commit();
        }
        const uint32_t stg  = sb + (it & 1) * GS_STAGE;
        const uint32_t aAhi = stg;
        const uint32_t aAlo = stg + 8192;
        const uint32_t aB   = stg + 16384;

#pragma unroll
        for (int ks = 0; ks < 2; ks++) {
            const int k16 = ks * 16;
            const int arow_off = r8 + ((tile & 1) << 3);
            const int aseg = (k16 + ((tile >= 2) ? 8 : 0)) >> 3;
            const int brow_off = r8 + ((tile >> 1) << 3);
            const int bseg = (k16 + ((tile & 1) ? 8 : 0)) >> 3;

            uint32_t ah[4][4], al[4][4], bf[2][4];
#pragma unroll
            for (int mi = 0; mi < 4; mi++) {
                int row = wm * 64 + mi * 16 + arow_off;
                uint32_t off = (uint32_t)(row * 64 + ((aseg ^ ((row >> 1) & 3)) << 4));
                ldm_x4(ah[mi], aAhi + off);
                ldm_x4(al[mi], aAlo + off);
            }
#pragma unroll
            for (int p = 0; p < 2; p++) {
                int row = wn * 32 + p * 16 + brow_off;
                uint32_t off = (uint32_t)(row * 64 + ((bseg ^ ((row >> 1) & 3)) << 4));
                ldm_x4(bf[p], aB + off);
            }

#pragma unroll
            for (int mi = 0; mi < 4; mi++)
#pragma unroll
                for (int ni = 0; ni < 4; ni++)
                    mma_fp16(acc[mi][ni], ah[mi], &bf[ni >> 1][(ni & 1) * 2]);
#pragma unroll
            for (int mi = 0; mi < 4; mi++)
#pragma unroll
                for (int ni = 0; ni < 4; ni++)
                    mma_fp16(acc[mi][ni], al[mi], &bf[ni >> 1][(ni & 1) * 2]);
        }
    }

    const int mrb = m0 + wm * 64;
    const int ncb = n0 + wn * 32;
#pragma unroll
    for (int mi = 0; mi < 4; mi++) {
#pragma unroll
        for (int ni = 0; ni < 4; ni++) {
            int n = ncb + ni * 8 + (lane & 3) * 2;
            float2 bv = *(const float2*)&bias[n];
#pragma unroll
            for (int hf = 0; hf < 2; hf++) {
                int m = mrb + mi * 16 + (lane >> 2) + hf * 8;
                float c0 = acc[mi][ni][hf * 2 + 0] + bv.x;
                float c1 = acc[mi][ni][hf * 2 + 1] + bv.y;
                if (mode < 3) {
                    int bb = m & 1, s = m >> 1;
                    int hh = n >> 6, d = n & 63;
                    size_t addr = (((size_t)bb * NH + hh) * SEQ + s) * DH + d;
                    if (mode == 0) {
                        __half h0 = __float2half(c0);
                        __half h1 = __float2half(c1);
                        *(__half2*)&g_Qh[addr] = __halves2half2(h0, h1);
                        *(__half2*)&g_Ql[addr] = __halves2half2(
                            __float2half(c0 - __half2float(h0)),
                            __float2half(c1 - __half2float(h1)));
                    } else {
                        __half* C = (mode == 1) ? g_Ks : g_Vs;
                        *(__half2*)&C[addr] =
                            __halves2half2(__float2half(c0), __float2half(c1));
                    }
                } else {
                    int bb = m >> 13, s = m & (SEQ - 1);
                    *(float2*)&Cout[(size_t)(s * BATCH + bb) * EMB + n] = make_float2(c0, c1);
                }
            }
        }
    }
#undef GPREFETCH
}

// ============================================================
// Attention v4: fp16 2-term. 128 threads, 4 warps; warp = 16 q-rows x 64 keys.
// Q fp16 hi/lo (exact); K,V single fp16. Smem 24KB: K0|K1|V (8KB each);
// Q staged initially into K1+V region. 4 CTAs/SM.
// ============================================================
#define AT_K0 0
#define AT_K1 8192
#define AT_V  16384

__device__ __forceinline__ int blk_of(int j, int nb, const int* __restrict__ ri) {
    if (j < NGLOB) return j;
    if (j < NGLOB + NWIN) return (nb + j - 3 + NBLK) & (NBLK - 1);
    return ri[nb * 3 + (j - 5)];
}

__global__ __launch_bounds__(128, 4)
void attn_mma(const int* __restrict__ rand_idx)
{
    __shared__ char smb[24576];
    const uint32_t sb = smem_u32(smb);

    const int nb  = blockIdx.x;
    const int bh  = blockIdx.y;
    const int tid = threadIdx.x;
    const int w    = tid >> 5;
    const int lane = tid & 31;
    const int tile = lane >> 3;
    const int r8   = lane & 7;
    const int sel  = lane >> 3;
    const int qrow = lane >> 2;
    const int qc   = (lane & 3) * 2;
    const size_t base = (size_t)bh * SEQ * DH;
    const float CC = 0.18033688011112042f;   // (1/8) * log2(e)

    // stage one 64x64 fp16 single tile (8KB)
#define STAGE_S(DST, SRC, ROWBASE)                                               \
    {                                                                            \
        _Pragma("unroll")                                                        \
        for (int i = 0; i < 4; i++) {                                            \
            int idx = tid + 128 * i;                                             \
            int row = idx >> 3;                                                  \
            int seg = idx & 7;                                                   \
            cp16((DST) + row * 128 + ((seg ^ (row & 7)) << 4),                   \
                 (SRC) + (ROWBASE) + (size_t)row * 64 + seg * 8);                \
        }                                                                        \
    }

    // ---- preload: Q hi/lo (into K1+V region) + K(0) ----
    STAGE_S(sb + AT_K1, g_Qh, base + (size_t)nb * BLK * DH);
    STAGE_S(sb + AT_V,  g_Ql, base + (size_t)nb * BLK * DH);
    STAGE_S(sb + AT_K0, g_Ks, base + (size_t)blk_of(0, nb, rand_idx) * BLK * DH);
    cp_commit();
    cp_wait<0>();
    __syncthreads();

    // ---- hoist Q fragments ----
    uint32_t qh[4][4], ql[4][4];
#pragma unroll
    for (int ks = 0; ks < 4; ks++) {
        const int arow = 16 * w + r8 + ((tile & 1) << 3);
        const int aseg = ks * 2 + ((tile >> 1) & 1);
        const uint32_t aoff = (uint32_t)(arow * 128 + ((aseg ^ (arow & 7)) << 4));
        ldm_x4(qh[ks], sb + AT_K1 + aoff);
        ldm_x4(ql[ks], sb + AT_V + aoff);
    }
    __syncthreads();   // Q regions free -> V/K1 can load

    // issue V(0), K(1)
    STAGE_S(sb + AT_V,  g_Vs, base + (size_t)blk_of(0, nb, rand_idx) * BLK * DH);
    cp_commit();
    STAGE_S(sb + AT_K1, g_Ks, base + (size_t)blk_of(1, nb, rand_idx) * BLK * DH);
    cp_commit();

    float of[8][4];
#pragma unroll
    for (int i = 0; i < 8; i++)
#pragma unroll
        for (int jj = 0; jj < 4; jj++) of[i][jj] = 0.f;
    float mst0 = -1e30f, mst1 = -1e30f, lst0 = 0.f, lst1 = 0.f;

    for (int j = 0; j < MBL; j++) {
        const uint32_t kbuf = sb + ((j & 1) ? AT_K1 : AT_K0);

        // ---- QK^T: 16 rows x 64 keys, 2-term ----
        float sf[8][4];
#pragma unroll
        for (int nf = 0; nf < 8; nf++)
#pragma unroll
            for (int r = 0; r < 4; r++) sf[nf][r] = 0.f;

#pragma unroll
        for (int ks = 0; ks < 4; ks++) {
            uint32_t kh[4][4];
#pragma unroll
            for (int p = 0; p < 4; p++) {
                const int brow = 16 * p + r8 + ((tile >> 1) << 3);
                const int bseg = ks * 2 + (tile & 1);
                const uint32_t boff = (uint32_t)(brow * 128 + ((bseg ^ (brow & 7)) << 4));
                ldm_x4(kh[p], kbuf + boff);
            }
#pragma unroll
            for (int nf = 0; nf < 8; nf++)
                mma_fp16(sf[nf], qh[ks], &kh[nf >> 1][(nf & 1) * 2]);
#pragma unroll
            for (int nf = 0; nf < 8; nf++)
                mma_fp16(sf[nf], ql[ks], &kh[nf >> 1][(nf & 1) * 2]);
        }

        // ---- warp-local online softmax ----
        float rmax0 = sf[0][0], rmax1 = sf[0][2];
#pragma unroll
        for (int nf = 0; nf < 8; nf++) {
            rmax0 = fmaxf(rmax0, fmaxf(sf[nf][0], sf[nf][1]));
            rmax1 = fmaxf(rmax1, fmaxf(sf[nf][2], sf[nf][3]));
        }
        rmax0 = fmaxf(rmax0, __shfl_xor_sync(0xffffffffu, rmax0, 1));
        rmax0 = fmaxf(rmax0, __shfl_xor_sync(0xffffffffu, rmax0, 2));
        rmax1 = fmaxf(rmax1, __shfl_xor_sync(0xffffffffu, rmax1, 1));
        rmax1 = fmaxf(rmax1, __shfl_xor_sync(0xffffffffu, rmax1, 2));
        const float mn0 = fmaxf(mst0, rmax0);
        const float mn1 = fmaxf(mst1, rmax1);
        const float al0 = exp2f((mst0 - mn0) * CC);
        const float al1 = exp2f((mst1 - mn1) * CC);

        float rsum0 = 0.f, rsum1 = 0.f;
        uint32_t pah[4][4], pal[4][4];
#pragma unroll
        for (int t = 0; t < 4; t++) {
#pragma unroll
            for (int hl = 0; hl < 2; hl++) {
                int nf = 2 * t + hl;
                float p0 = exp2f((sf[nf][0] - mn0) * CC);
                float p1 = exp2f((sf[nf][1] - mn0) * CC);
                float p2 = exp2f((sf[nf][2] - mn1) * CC);
                float p3 = exp2f((sf[nf][3] - mn1) * CC);
                rsum0 += p0 + p1;
                rsum1 += p2 + p3;
                uint32_t h01 = pack_hf2(p0, p1);
                uint32_t h23 = pack_hf2(p2, p3);
                __half2 hv01 = *(__half2*)&h01;
                __half2 hv23 = *(__half2*)&h23;
                pah[t][2 * hl + 0] = h01;
                pah[t][2 * hl + 1] = h23;
                pal[t][2 * hl + 0] = pack_hf2(p0 - __half2float(hv01.x),
                                              p1 - __half2float(hv01.y));
                pal[t][2 * hl + 1] = pack_hf2(p2 - __half2float(hv23.x),
                                              p3 - __half2float(hv23.y));
            }
        }
        rsum0 += __shfl_xor_sync(0xffffffffu, rsum0, 1);
        rsum0 += __shfl_xor_sync(0xffffffffu, rsum0, 2);
        rsum1 += __shfl_xor_sync(0xffffffffu, rsum1, 1);
        rsum1 += __shfl_xor_sync(0xffffffffu, rsum1, 2);
        lst0 = lst0 * al0 + rsum0;
        lst1 = lst1 * al1 + rsum1;
        mst0 = mn0;
        mst1 = mn1;
#pragma unroll
        for (int nf = 0; nf < 8; nf++) {
            of[nf][0] *= al0; of[nf][1] *= al0;
            of[nf][2] *= al1; of[nf][3] *= al1;
        }

        // ---- V(j) ready? ----
        if (j < MBL - 1) cp_wait<1>(); else cp_wait<0>();
        __syncthreads();

        // ---- PV: O += P * V, 2-term (P hi/lo exact, V single) ----
#pragma unroll
        for (int t = 0; t < 4; t++) {
            const int vkey = 16 * t + (lane & 7) + ((sel & 1) << 3);
#pragma unroll
            for (int g = 0; g < 4; g++) {
                const int vseg = 2 * g + (sel >> 1);
                const uint32_t voff = (uint32_t)(vkey * 128 + ((vseg ^ (vkey & 7)) << 4));
                uint32_t vh[4];
                ldm_x4t(vh, sb + AT_V + voff);
                mma_fp16(of[2 * g + 0], pah[t], &vh[0]);
                mma_fp16(of[2 * g + 1], pah[t], &vh[2]);
                mma_fp16(of[2 * g + 0], pal[t], &vh[0]);
                mma_fp16(of[2 * g + 1], pal[t], &vh[2]);
            }
        }

        if (j < MBL - 1) {
            cp_wait<0>();      // K(j+1) arrived
            __syncthreads();   // V buffer free
            size_t v_b = base + (size_t)blk_of(j + 1, nb, rand_idx) * BLK * DH;
            STAGE_S(sb + AT_V, g_Vs, v_b);
            cp_commit();
            if (j < MBL - 2) {
                size_t k_b = base + (size_t)blk_of(j + 2, nb, rand_idx) * BLK * DH;
                STAGE_S(sb + ((j & 1) ? AT_K1 : AT_K0), g_Ks, k_b);
                cp_commit();
            }
        }
    }

    // ---- epilogue: store normalized O as fp16 hi/lo (out-proj A operand) ----
    const int b = bh >> 3, h = bh & 7;
    const int r0 = 16 * w + qrow;
    const float inv0 = 1.f / lst0;
    const float inv1 = 1.f / lst1;
    __half* AOh = g_Inh + 3 * IN_STRIDE;
    __half* AOl = g_Inl + 3 * IN_STRIDE;
#pragma unroll
    for (int nf = 0; nf < 8; nf++) {
        int d = nf * 8 + qc;
        float v00 = of[nf][0] * inv0, v01 = of[nf][1] * inv0;
        float v10 = of[nf][2] * inv1, v11 = of[nf][3] * inv1;
        size_t a0 = (size_t)(b * SEQ + nb * BLK + r0) * EMB + h * DH + d;
        size_t a1 = (size_t)(b * SEQ + nb * BLK + r0 + 8) * EMB + h * DH + d;
        __half h00 = __float2half(v00), h01 = __float2half(v01);
        __half h10 = __float2half(v10), h11 = __float2half(v11);
        *(__half2*)&AOh[a0] = __halves2half2(h00, h01);
        *(__half2*)&AOh[a1] = __halves2half2(h10, h11);
        *(__half2*)&AOl[a0] = __halves2half2(
            __float2half(v00 - __half2float(h00)),
            __float2half(v01 - __half2float(h01)));
        *(__half2*)&AOl[a1] = __halves2half2(
            __float2half(v10 - __half2float(h10)),
            __float2half(v11 - __half2float(h11)));
    }
#undef STAGE_S
}

// ============================================================
extern "C" void kernel_launch(void* const* d_in, const int* in_sizes, int n_in,
                              void* d_out, int out_size)
{
    const float* query   = (const float*)d_in[0];
    const float* key_inp = (const float*)d_in[1];
    const float* value   = (const float*)d_in[2];
    const float* q_w     = (const float*)d_in[3];
    const float* k_w     = (const float*)d_in[4];
    const float* v_w     = (const float*)d_in[5];
    const float* q_b     = (const float*)d_in[6];
    const float* k_b     = (const float*)d_in[7];
    const float* v_b     = (const float*)d_in[8];
    const float* out_w   = (const float*)d_in[9];
    const float* out_b   = (const float*)d_in[10];
    const int*   rand_idx= (const int*)d_in[11];
    float* out = (float*)d_out;

    static bool attr_set = false;
    if (!attr_set) {
        cudaFuncSetAttribute(gemm_mma,
                             cudaFuncAttributeMaxDynamicSharedMemorySize, GS_SMEM);
        attr_set = true;
    }

    conv_all<<<8192, 256>>>(q_w, k_w, v_w, out_w, query, key_inp, value);

    dim3 gQKV(128, 24);
    gemm_mma<<<gQKV, 128, GS_SMEM>>>(q_b, k_b, v_b, out_b, out, 0);

    dim3 gAttn(NBLK, BATCH * NH);
    attn_mma<<<gAttn, 128>>>(rand_idx);

    dim3 gOut(128, 8);
    gemm_mma<<<gOut, 128, GS_SMEM>>>(q_b, k_b, v_b, out_b, out, 3);
}

// round 15
// speedup vs baseline: 2.3797x; 1.1408x over previous
#include <cuda_runtime.h>
#include <cuda_bf16.h>
#include <cuda_fp16.h>
#include <math.h>
#include <cstdint>

#define SEQ   8192
#define BATCH 2
#define EMB   512
#define NH    8
#define DH    64
#define NBLK  128      // SEQ / 64
#define BLK   64
#define MBL   8        // gathered blocks per query block
#define NGLOB 2
#define NWIN  3

#define IN_STRIDE ((size_t)16384 * 512)

// ---- device-global scratch (allocation-free) ----
// A-side activations, fp16 hi/lo: slots 0=q_in 1=k_in 2=v_in 3=attn_out
__device__ __half g_Inh[4 * IN_STRIDE];
__device__ __half g_Inl[4 * IN_STRIDE];
// post-projection Q/K/V single fp16, [b][h][s][d]
__device__ __half g_Qs[(size_t)BATCH * NH * SEQ * DH];
__device__ __half g_Ks[(size_t)BATCH * NH * SEQ * DH];
__device__ __half g_Vs[(size_t)BATCH * NH * SEQ * DH];
// fp16 single weights: [mat][n][k], mat: 0=q 1=k 2=v 3=out
__device__ __half g_Wh[4u * 512u * 512u];

// ============================================================
// helpers (baseline PTX only)
// ============================================================
__device__ __forceinline__ uint32_t smem_u32(const void* p) {
    uint32_t a;
    asm("{ .reg .u64 t; cvta.to.shared.u64 t, %1; cvt.u32.u64 %0, t; }"
        : "=r"(a) : "l"(p));
    return a;
}
__device__ __forceinline__ void ldm_x4(uint32_t* r, uint32_t addr) {
    asm volatile("ldmatrix.sync.aligned.m8n8.x4.shared.b16 {%0,%1,%2,%3}, [%4];"
                 : "=r"(r[0]), "=r"(r[1]), "=r"(r[2]), "=r"(r[3]) : "r"(addr));
}
__device__ __forceinline__ void ldm_x4t(uint32_t* r, uint32_t addr) {
    asm volatile("ldmatrix.sync.aligned.m8n8.x4.trans.shared.b16 {%0,%1,%2,%3}, [%4];"
                 : "=r"(r[0]), "=r"(r[1]), "=r"(r[2]), "=r"(r[3]) : "r"(addr));
}
__device__ __forceinline__ void mma_fp16(float* d, const uint32_t* a, const uint32_t* b) {
    asm volatile(
        "mma.sync.aligned.m16n8k16.row.col.f32.f16.f16.f32 "
        "{%0,%1,%2,%3}, {%4,%5,%6,%7}, {%8,%9}, {%0,%1,%2,%3};"
        : "+f"(d[0]), "+f"(d[1]), "+f"(d[2]), "+f"(d[3])
        : "r"(a[0]), "r"(a[1]), "r"(a[2]), "r"(a[3]), "r"(b[0]), "r"(b[1]));
}
__device__ __forceinline__ void cp16(uint32_t dst, const void* src) {
    asm volatile("cp.async.cg.shared.global [%0], [%1], 16;" :: "r"(dst), "l"(src) : "memory");
}
__device__ __forceinline__ void cp_commit() {
    asm volatile("cp.async.commit_group;" ::: "memory");
}
template<int N> __device__ __forceinline__ void cp_wait() {
    asm volatile("cp.async.wait_group %0;" :: "n"(N) : "memory");
}
__device__ __forceinline__ uint32_t pack_hf2(float x, float y) {
    __half2 v = __halves2half2(__float2half(x), __float2half(y));
    return *(uint32_t*)&v;
}

// ============================================================
// Fused conversion: weights (fp32 -> single fp16, [mat][n][k]) +
// inputs (fp32 -> fp16 hi/lo).
// ============================================================
__global__ void conv_all(const float* __restrict__ qw, const float* __restrict__ kw,
                         const float* __restrict__ vw, const float* __restrict__ ow,
                         const float* __restrict__ qi, const float* __restrict__ ki,
                         const float* __restrict__ vi)
{
    const int bx = blockIdx.x;
    if (bx < 2048) {
        const int mat = bx >> 9;
        const int n   = bx & 511;
        const float* src = (mat == 0) ? qw : (mat == 1) ? kw : (mat == 2) ? vw : ow;
        for (int k = threadIdx.x; k < 512; k += 256) {
            float v;
            if (mat < 3) v = src[((size_t)(n >> 6) * 512 + k) * 64 + (n & 63)];
            else         v = src[(size_t)n * 512 + k];
            g_Wh[(size_t)mat * 262144 + (size_t)n * 512 + k] = __float2half(v);
        }
    } else {
        const int bi  = bx - 2048;
        const int mat = bi >> 11;
        const int blk = bi & 2047;
        const float* src = (mat == 0) ? qi : (mat == 1) ? ki : vi;
        __half* dh = g_Inh + (size_t)mat * IN_STRIDE;
        __half* dl = g_Inl + (size_t)mat * IN_STRIDE;
#pragma unroll
        for (int i = 0; i < 4; i++) {
            size_t o4 = (size_t)blk * 1024 + i * 256 + threadIdx.x;
            float4 x = *(const float4*)&src[o4 * 4];
            __half h0 = __float2half(x.x), h1 = __float2half(x.y);
            __half h2 = __float2half(x.z), h3 = __float2half(x.w);
            __half l0 = __float2half(x.x - __half2float(h0));
            __half l1 = __float2half(x.y - __half2float(h1));
            __half l2 = __float2half(x.z - __half2float(h2));
            __half l3 = __float2half(x.w - __half2float(h3));
            *(__half2*)&dh[o4 * 4 + 0] = __halves2half2(h0, h1);
            *(__half2*)&dh[o4 * 4 + 2] = __halves2half2(h2, h3);
            *(__half2*)&dl[o4 * 4 + 0] = __halves2half2(l0, l1);
            *(__half2*)&dl[o4 * 4 + 2] = __halves2half2(l2, l3);
        }
    }
}

// ============================================================
// HMMA GEMM (R13-proven): fp16 2-term, CTA 128x64, 128 thr, 4 CTAs/SM.
// Epilogue: modes 0-2 -> single fp16 Q/K/V; mode 3 -> fp32 out.
// ============================================================
#define GS_STAGE 20480
#define GS_SMEM  (2 * GS_STAGE)   // 40 KB

__global__ __launch_bounds__(128, 4)
void gemm_mma(const float* __restrict__ qb, const float* __restrict__ kb,
              const float* __restrict__ vb, const float* __restrict__ ob,
              float* __restrict__ Cout, int mode_base)
{
    extern __shared__ char gsm[];
    const uint32_t sb = smem_u32(gsm);
    const int tid  = threadIdx.x;
    const int wid  = tid >> 5;
    const int lane = tid & 31;
    const int wm   = wid >> 1;
    const int wn   = wid & 1;
    const int m0   = blockIdx.x * 128;
    const int mode = mode_base + (blockIdx.y >> 3);
    const int n0   = (blockIdx.y & 7) * 64;

    const __half* __restrict__ Ah = g_Inh + (size_t)mode * IN_STRIDE;
    const __half* __restrict__ Al = g_Inl + (size_t)mode * IN_STRIDE;
    const __half* __restrict__ Bw = g_Wh  + (size_t)mode * 262144;
    const float* __restrict__ bias = (mode == 0) ? qb : (mode == 1) ? kb
                                   : (mode == 2) ? vb : ob;

#define GPREFETCH(K0, ST)                                                        \
    {                                                                            \
        uint32_t d0 = sb + (ST) * GS_STAGE;                                      \
        _Pragma("unroll")                                                        \
        for (int i = 0; i < 8; i++) {                                            \
            int idx = tid + 128 * i;                                             \
            int mt  = idx >> 9;                                                  \
            int row = (idx >> 2) & 127;                                          \
            int seg = idx & 3;                                                   \
            const __half* src = (mt ? Al : Ah)                                   \
                + (size_t)(m0 + row) * 512 + (K0) + seg * 8;                     \
            cp16(d0 + mt * 8192 + row * 64 + ((seg ^ ((row >> 1) & 3)) << 4),    \
                 src);                                                           \
        }                                                                        \
        _Pragma("unroll")                                                        \
        for (int i = 0; i < 2; i++) {                                            \
            int r2  = tid + 128 * i;                                             \
            int row = r2 >> 2;                                                   \
            int seg = r2 & 3;                                                    \
            const __half* src = Bw + (size_t)(n0 + row) * 512 + (K0) + seg * 8;  \
            cp16(d0 + 16384 + row * 64 + ((seg ^ ((row >> 1) & 3)) << 4), src);  \
        }                                                                        \
    }

    GPREFETCH(0, 0);
    cp_commit();

    float acc[4][4][4];
#pragma unroll
    for (int i = 0; i < 4; i++)
#pragma unroll
        for (int j = 0; j < 4; j++)
#pragma unroll
            for (int r = 0; r < 4; r++) acc[i][j][r] = 0.f;

    const int tile = lane >> 3;
    const int r8   = lane & 7;

    for (int it = 0; it < 16; it++) {
        cp_wait<0>();
        __syncthreads();
        if (it + 1 < 16) {
            GPREFETCH((it + 1) * 32, (it + 1) & 1);
            cp_commit();
        }
        const uint32_t stg  = sb + (it & 1) * GS_STAGE;
        const uint32_t aAhi = stg;
        const uint32_t aAlo = stg + 8192;
        const uint32_t aB   = stg + 16384;

#pragma unroll
        for (int ks = 0; ks < 2; ks++) {
            const int k16 = ks * 16;
            const int arow_off = r8 + ((tile & 1) << 3);
            const int aseg = (k16 + ((tile >= 2) ? 8 : 0)) >> 3;
            const int brow_off = r8 + ((tile >> 1) << 3);
            const int bseg = (k16 + ((tile & 1) ? 8 : 0)) >> 3;

            uint32_t ah[4][4], al[4][4], bf[2][4];
#pragma unroll
            for (int mi = 0; mi < 4; mi++) {
                int row = wm * 64 + mi * 16 + arow_off;
                uint32_t off = (uint32_t)(row * 64 + ((aseg ^ ((row >> 1) & 3)) << 4));
                ldm_x4(ah[mi], aAhi + off);
                ldm_x4(al[mi], aAlo + off);
            }
#pragma unroll
            for (int p = 0; p < 2; p++) {
                int row = wn * 32 + p * 16 + brow_off;
                uint32_t off = (uint32_t)(row * 64 + ((bseg ^ ((row >> 1) & 3)) << 4));
                ldm_x4(bf[p], aB + off);
            }

#pragma unroll
            for (int mi = 0; mi < 4; mi++)
#pragma unroll
                for (int ni = 0; ni < 4; ni++)
                    mma_fp16(acc[mi][ni], ah[mi], &bf[ni >> 1][(ni & 1) * 2]);
#pragma unroll
            for (int mi = 0; mi < 4; mi++)
#pragma unroll
                for (int ni = 0; ni < 4; ni++)
                    mma_fp16(acc[mi][ni], al[mi], &bf[ni >> 1][(ni & 1) * 2]);
        }
    }

    const int mrb = m0 + wm * 64;
    const int ncb = n0 + wn * 32;
#pragma unroll
    for (int mi = 0; mi < 4; mi++) {
#pragma unroll
        for (int ni = 0; ni < 4; ni++) {
            int n = ncb + ni * 8 + (lane & 3) * 2;
            float2 bv = *(const float2*)&bias[n];
#pragma unroll
            for (int hf = 0; hf < 2; hf++) {
                int m = mrb + mi * 16 + (lane >> 2) + hf * 8;
                float c0 = acc[mi][ni][hf * 2 + 0] + bv.x;
                float c1 = acc[mi][ni][hf * 2 + 1] + bv.y;
                if (mode < 3) {
                    int bb = m & 1, s = m >> 1;
                    int hh = n >> 6, d = n & 63;
                    size_t addr = (((size_t)bb * NH + hh) * SEQ + s) * DH + d;
                    __half* C = (mode == 0) ? g_Qs : (mode == 1) ? g_Ks : g_Vs;
                    *(__half2*)&C[addr] =
                        __halves2half2(__float2half(c0), __float2half(c1));
                } else {
                    int bb = m >> 13, s = m & (SEQ - 1);
                    *(float2*)&Cout[(size_t)(s * BATCH + bb) * EMB + n] = make_float2(c0, c1);
                }
            }
        }
    }
#undef GPREFETCH
}

// ============================================================
// Attention v5: pure fp16 (fp32 acc). 128 threads, 4 warps;
// warp = 16 q-rows x 64 keys. Smem 24KB: K0|K1|V (8KB each).
// QK 32 MMAs/iter, PV 32 MMAs/iter.
// ============================================================
#define AT_K0 0
#define AT_K1 8192
#define AT_V  16384

__device__ __forceinline__ int blk_of(int j, int nb, const int* __restrict__ ri) {
    if (j < NGLOB) return j;
    if (j < NGLOB + NWIN) return (nb + j - 3 + NBLK) & (NBLK - 1);
    return ri[nb * 3 + (j - 5)];
}

__global__ __launch_bounds__(128, 4)
void attn_mma(const int* __restrict__ rand_idx)
{
    __shared__ char smb[24576];
    const uint32_t sb = smem_u32(smb);

    const int nb  = blockIdx.x;
    const int bh  = blockIdx.y;
    const int tid = threadIdx.x;
    const int w    = tid >> 5;
    const int lane = tid & 31;
    const int tile = lane >> 3;
    const int r8   = lane & 7;
    const int sel  = lane >> 3;
    const int qrow = lane >> 2;
    const int qc   = (lane & 3) * 2;
    const size_t base = (size_t)bh * SEQ * DH;
    const float CC = 0.18033688011112042f;   // (1/8) * log2(e)

    // stage one 64x64 fp16 tile (8KB)
#define STAGE_S(DST, SRC, ROWBASE)                                               \
    {                                                                            \
        _Pragma("unroll")                                                        \
        for (int i = 0; i < 4; i++) {                                            \
            int idx = tid + 128 * i;                                             \
            int row = idx >> 3;                                                  \
            int seg = idx & 7;                                                   \
            cp16((DST) + row * 128 + ((seg ^ (row & 7)) << 4),                   \
                 (SRC) + (ROWBASE) + (size_t)row * 64 + seg * 8);                \
        }                                                                        \
    }

    // ---- preload: Q (into V region) + K(0) ----
    STAGE_S(sb + AT_V,  g_Qs, base + (size_t)nb * BLK * DH);
    STAGE_S(sb + AT_K0, g_Ks, base + (size_t)blk_of(0, nb, rand_idx) * BLK * DH);
    cp_commit();
    cp_wait<0>();
    __syncthreads();

    // ---- hoist Q fragments ----
    uint32_t qh[4][4];
#pragma unroll
    for (int ks = 0; ks < 4; ks++) {
        const int arow = 16 * w + r8 + ((tile & 1) << 3);
        const int aseg = ks * 2 + ((tile >> 1) & 1);
        const uint32_t aoff = (uint32_t)(arow * 128 + ((aseg ^ (arow & 7)) << 4));
        ldm_x4(qh[ks], sb + AT_V + aoff);
    }
    __syncthreads();   // Q region free -> V can load

    // issue V(0), K(1)
    STAGE_S(sb + AT_V,  g_Vs, base + (size_t)blk_of(0, nb, rand_idx) * BLK * DH);
    cp_commit();
    STAGE_S(sb + AT_K1, g_Ks, base + (size_t)blk_of(1, nb, rand_idx) * BLK * DH);
    cp_commit();

    float of[8][4];
#pragma unroll
    for (int i = 0; i < 8; i++)
#pragma unroll
        for (int jj = 0; jj < 4; jj++) of[i][jj] = 0.f;
    float mst0 = -1e30f, mst1 = -1e30f, lst0 = 0.f, lst1 = 0.f;

    for (int j = 0; j < MBL; j++) {
        const uint32_t kbuf = sb + ((j & 1) ? AT_K1 : AT_K0);

        // ---- QK^T: 16 rows x 64 keys ----
        float sf[8][4];
#pragma unroll
        for (int nf = 0; nf < 8; nf++)
#pragma unroll
            for (int r = 0; r < 4; r++) sf[nf][r] = 0.f;

#pragma unroll
        for (int ks = 0; ks < 4; ks++) {
            uint32_t kh[4][4];
#pragma unroll
            for (int p = 0; p < 4; p++) {
                const int brow = 16 * p + r8 + ((tile >> 1) << 3);
                const int bseg = ks * 2 + (tile & 1);
                const uint32_t boff = (uint32_t)(brow * 128 + ((bseg ^ (brow & 7)) << 4));
                ldm_x4(kh[p], kbuf + boff);
            }
#pragma unroll
            for (int nf = 0; nf < 8; nf++)
                mma_fp16(sf[nf], qh[ks], &kh[nf >> 1][(nf & 1) * 2]);
        }

        // ---- warp-local online softmax ----
        float rmax0 = sf[0][0], rmax1 = sf[0][2];
#pragma unroll
        for (int nf = 0; nf < 8; nf++) {
            rmax0 = fmaxf(rmax0, fmaxf(sf[nf][0], sf[nf][1]));
            rmax1 = fmaxf(rmax1, fmaxf(sf[nf][2], sf[nf][3]));
        }
        rmax0 = fmaxf(rmax0, __shfl_xor_sync(0xffffffffu, rmax0, 1));
        rmax0 = fmaxf(rmax0, __shfl_xor_sync(0xffffffffu, rmax0, 2));
        rmax1 = fmaxf(rmax1, __shfl_xor_sync(0xffffffffu, rmax1, 1));
        rmax1 = fmaxf(rmax1, __shfl_xor_sync(0xffffffffu, rmax1, 2));
        const float mn0 = fmaxf(mst0, rmax0);
        const float mn1 = fmaxf(mst1, rmax1);
        const float al0 = exp2f((mst0 - mn0) * CC);
        const float al1 = exp2f((mst1 - mn1) * CC);

        float rsum0 = 0.f, rsum1 = 0.f;
        uint32_t pah[4][4];
#pragma unroll
        for (int t = 0; t < 4; t++) {
#pragma unroll
            for (int hl = 0; hl < 2; hl++) {
                int nf = 2 * t + hl;
                float p0 = exp2f((sf[nf][0] - mn0) * CC);
                float p1 = exp2f((sf[nf][1] - mn0) * CC);
                float p2 = exp2f((sf[nf][2] - mn1) * CC);
                float p3 = exp2f((sf[nf][3] - mn1) * CC);
                rsum0 += p0 + p1;
                rsum1 += p2 + p3;
                pah[t][2 * hl + 0] = pack_hf2(p0, p1);
                pah[t][2 * hl + 1] = pack_hf2(p2, p3);
            }
        }
        rsum0 += __shfl_xor_sync(0xffffffffu, rsum0, 1);
        rsum0 += __shfl_xor_sync(0xffffffffu, rsum0, 2);
        rsum1 += __shfl_xor_sync(0xffffffffu, rsum1, 1);
        rsum1 += __shfl_xor_sync(0xffffffffu, rsum1, 2);
        lst0 = lst0 * al0 + rsum0;
        lst1 = lst1 * al1 + rsum1;
        mst0 = mn0;
        mst1 = mn1;
#pragma unroll
        for (int nf = 0; nf < 8; nf++) {
            of[nf][0] *= al0; of[nf][1] *= al0;
            of[nf][2] *= al1; of[nf][3] *= al1;
        }

        // ---- V(j) ready? ----
        if (j < MBL - 1) cp_wait<1>(); else cp_wait<0>();
        __syncthreads();

        // ---- PV: O += P * V ----
#pragma unroll
        for (int t = 0; t < 4; t++) {
            const int vkey = 16 * t + (lane & 7) + ((sel & 1) << 3);
#pragma unroll
            for (int g = 0; g < 4; g++) {
                const int vseg = 2 * g + (sel >> 1);
                const uint32_t voff = (uint32_t)(vkey * 128 + ((vseg ^ (vkey & 7)) << 4));
                uint32_t vh[4];
                ldm_x4t(vh, sb + AT_V + voff);
                mma_fp16(of[2 * g + 0], pah[t], &vh[0]);
                mma_fp16(of[2 * g + 1], pah[t], &vh[2]);
            }
        }

        if (j < MBL - 1) {
            cp_wait<0>();      // K(j+1) arrived
            __syncthreads();   // V buffer free
            size_t v_b = base + (size_t)blk_of(j + 1, nb, rand_idx) * BLK * DH;
            STAGE_S(sb + AT_V, g_Vs, v_b);
            cp_commit();
            if (j < MBL - 2) {
                size_t k_b = base + (size_t)blk_of(j + 2, nb, rand_idx) * BLK * DH;
                STAGE_S(sb + ((j & 1) ? AT_K1 : AT_K0), g_Ks, k_b);
                cp_commit();
            }
        }
    }

    // ---- epilogue: store normalized O as fp16 hi/lo (out-proj A operand) ----
    const int b = bh >> 3, h = bh & 7;
    const int r0 = 16 * w + qrow;
    const float inv0 = 1.f / lst0;
    const float inv1 = 1.f / lst1;
    __half* AOh = g_Inh + 3 * IN_STRIDE;
    __half* AOl = g_Inl + 3 * IN_STRIDE;
#pragma unroll
    for (int nf = 0; nf < 8; nf++) {
        int d = nf * 8 + qc;
        float v00 = of[nf][0] * inv0, v01 = of[nf][1] * inv0;
        float v10 = of[nf][2] * inv1, v11 = of[nf][3] * inv1;
        size_t a0 = (size_t)(b * SEQ + nb * BLK + r0) * EMB + h * DH + d;
        size_t a1 = (size_t)(b * SEQ + nb * BLK + r0 + 8) * EMB + h * DH + d;
        __half h00 = __float2half(v00), h01 = __float2half(v01);
        __half h10 = __float2half(v10), h11 = __float2half(v11);
        *(__half2*)&AOh[a0] = __halves2half2(h00, h01);
        *(__half2*)&AOh[a1] = __halves2half2(h10, h11);
        *(__half2*)&AOl[a0] = __halves2half2(
            __float2half(v00 - __half2float(h00)),
            __float2half(v01 - __half2float(h01)));
        *(__half2*)&AOl[a1] = __halves2half2(
            __float2half(v10 - __half2float(h10)),
            __float2half(v11 - __half2float(h11)));
    }
#undef STAGE_S
}

// ============================================================
extern "C" void kernel_launch(void* const* d_in, const int* in_sizes, int n_in,
                              void* d_out, int out_size)
{
    const float* query   = (const float*)d_in[0];
    const float* key_inp = (const float*)d_in[1];
    const float* value   = (const float*)d_in[2];
    const float* q_w     = (const float*)d_in[3];
    const float* k_w     = (const float*)d_in[4];
    const float* v_w     = (const float*)d_in[5];
    const float* q_b     = (const float*)d_in[6];
    const float* k_b     = (const float*)d_in[7];
    const float* v_b     = (const float*)d_in[8];
    const float* out_w   = (const float*)d_in[9];
    const float* out_b   = (const float*)d_in[10];
    const int*   rand_idx= (const int*)d_in[11];
    float* out = (float*)d_out;

    static bool attr_set = false;
    if (!attr_set) {
        cudaFuncSetAttribute(gemm_mma,
                             cudaFuncAttributeMaxDynamicSharedMemorySize, GS_SMEM);
        attr_set = true;
    }

    conv_all<<<8192, 256>>>(q_w, k_w, v_w, out_w, query, key_inp, value);

    dim3 gQKV(128, 24);
    gemm_mma<<<gQKV, 128, GS_SMEM>>>(q_b, k_b, v_b, out_b, out, 0);

    dim3 gAttn(NBLK, BATCH * NH);
    attn_mma<<<gAttn, 128>>>(rand_idx);

    dim3 gOut(128, 8);
    gemm_mma<<<gOut, 128, GS_SMEM>>>(q_b, k_b, v_b, out_b, out, 3);
}

// round 16
// speedup vs baseline: 2.7701x; 1.1640x over previous
#include <cuda_runtime.h>
#include <cuda_bf16.h>
#include <cuda_fp16.h>
#include <math.h>
#include <cstdint>

#define SEQ   8192
#define BATCH 2
#define EMB   512
#define NH    8
#define DH    64
#define NBLK  128      // SEQ / 64
#define BLK   64
#define MBL   8        // gathered blocks per query block
#define NGLOB 2
#define NWIN  3

#define IN_STRIDE ((size_t)16384 * 512)

// ---- device-global scratch (allocation-free) ----
// A-side activations, fp16 hi/lo: slots 0=q_in 1=k_in 2=v_in 3=attn_out
// (lo is only consumed for slots 0,1; slot 3 stores hi only)
__device__ __half g_Inh[4 * IN_STRIDE];
__device__ __half g_Inl[4 * IN_STRIDE];
// post-projection Q/K/V single fp16, [b][h][s][d]
__device__ __half g_Qs[(size_t)BATCH * NH * SEQ * DH];
__device__ __half g_Ks[(size_t)BATCH * NH * SEQ * DH];
__device__ __half g_Vs[(size_t)BATCH * NH * SEQ * DH];
// fp16 single weights: [mat][n][k], mat: 0=q 1=k 2=v 3=out
__device__ __half g_Wh[4u * 512u * 512u];

// ============================================================
// helpers (baseline PTX only)
// ============================================================
__device__ __forceinline__ uint32_t smem_u32(const void* p) {
    uint32_t a;
    asm("{ .reg .u64 t; cvta.to.shared.u64 t, %1; cvt.u32.u64 %0, t; }"
        : "=r"(a) : "l"(p));
    return a;
}
__device__ __forceinline__ void ldm_x4(uint32_t* r, uint32_t addr) {
    asm volatile("ldmatrix.sync.aligned.m8n8.x4.shared.b16 {%0,%1,%2,%3}, [%4];"
                 : "=r"(r[0]), "=r"(r[1]), "=r"(r[2]), "=r"(r[3]) : "r"(addr));
}
__device__ __forceinline__ void ldm_x4t(uint32_t* r, uint32_t addr) {
    asm volatile("ldmatrix.sync.aligned.m8n8.x4.trans.shared.b16 {%0,%1,%2,%3}, [%4];"
                 : "=r"(r[0]), "=r"(r[1]), "=r"(r[2]), "=r"(r[3]) : "r"(addr));
}
__device__ __forceinline__ void mma_fp16(float* d, const uint32_t* a, const uint32_t* b) {
    asm volatile(
        "mma.sync.aligned.m16n8k16.row.col.f32.f16.f16.f32 "
        "{%0,%1,%2,%3}, {%4,%5,%6,%7}, {%8,%9}, {%0,%1,%2,%3};"
        : "+f"(d[0]), "+f"(d[1]), "+f"(d[2]), "+f"(d[3])
        : "r"(a[0]), "r"(a[1]), "r"(a[2]), "r"(a[3]), "r"(b[0]), "r"(b[1]));
}
__device__ __forceinline__ void cp16(uint32_t dst, const void* src) {
    asm volatile("cp.async.cg.shared.global [%0], [%1], 16;" :: "r"(dst), "l"(src) : "memory");
}
__device__ __forceinline__ void cp_commit() {
    asm volatile("cp.async.commit_group;" ::: "memory");
}
template<int N> __device__ __forceinline__ void cp_wait() {
    asm volatile("cp.async.wait_group %0;" :: "n"(N) : "memory");
}
__device__ __forceinline__ uint32_t pack_hf2(float x, float y) {
    __half2 v = __halves2half2(__float2half(x), __float2half(y));
    return *(uint32_t*)&v;
}

// ============================================================
// Fused conversion: weights (fp32 -> single fp16, [mat][n][k]) +
// inputs (fp32 -> fp16 hi/lo).
// ============================================================
__global__ void conv_all(const float* __restrict__ qw, const float* __restrict__ kw,
                         const float* __restrict__ vw, const float* __restrict__ ow,
                         const float* __restrict__ qi, const float* __restrict__ ki,
                         const float* __restrict__ vi)
{
    const int bx = blockIdx.x;
    if (bx < 2048) {
        const int mat = bx >> 9;
        const int n   = bx & 511;
        const float* src = (mat == 0) ? qw : (mat == 1) ? kw : (mat == 2) ? vw : ow;
        for (int k = threadIdx.x; k < 512; k += 256) {
            float v;
            if (mat < 3) v = src[((size_t)(n >> 6) * 512 + k) * 64 + (n & 63)];
            else         v = src[(size_t)n * 512 + k];
            g_Wh[(size_t)mat * 262144 + (size_t)n * 512 + k] = __float2half(v);
        }
    } else {
        const int bi  = bx - 2048;
        const int mat = bi >> 11;
        const int blk = bi & 2047;
        const float* src = (mat == 0) ? qi : (mat == 1) ? ki : vi;
        __half* dh = g_Inh + (size_t)mat * IN_STRIDE;
        __half* dl = g_Inl + (size_t)mat * IN_STRIDE;
        const bool need_lo = (mat < 2);   // V-projection is single-term
#pragma unroll
        for (int i = 0; i < 4; i++) {
            size_t o4 = (size_t)blk * 1024 + i * 256 + threadIdx.x;
            float4 x = *(const float4*)&src[o4 * 4];
            __half h0 = __float2half(x.x), h1 = __float2half(x.y);
            __half h2 = __float2half(x.z), h3 = __float2half(x.w);
            *(__half2*)&dh[o4 * 4 + 0] = __halves2half2(h0, h1);
            *(__half2*)&dh[o4 * 4 + 2] = __halves2half2(h2, h3);
            if (need_lo) {
                __half l0 = __float2half(x.x - __half2float(h0));
                __half l1 = __float2half(x.y - __half2float(h1));
                __half l2 = __float2half(x.z - __half2float(h2));
                __half l3 = __float2half(x.w - __half2float(h3));
                *(__half2*)&dl[o4 * 4 + 0] = __halves2half2(l0, l1);
                *(__half2*)&dl[o4 * 4 + 2] = __halves2half2(l2, l3);
            }
        }
    }
}

// ============================================================
// HMMA GEMM: fp16, CTA 128x64, 128 thr, 4 CTAs/SM.
// Modes 0,1 (Q,K proj): 2-term A (hi/lo).  Modes 2,3 (V, out): single-term.
// Epilogue: modes 0-2 -> single fp16 Q/K/V; mode 3 -> fp32 out.
// ============================================================
#define GS_STAGE 20480
#define GS_SMEM  (2 * GS_STAGE)   // 40 KB

__global__ __launch_bounds__(128, 4)
void gemm_mma(const float* __restrict__ qb, const float* __restrict__ kb,
              const float* __restrict__ vb, const float* __restrict__ ob,
              float* __restrict__ Cout, int mode_base)
{
    extern __shared__ char gsm[];
    const uint32_t sb = smem_u32(gsm);
    const int tid  = threadIdx.x;
    const int wid  = tid >> 5;
    const int lane = tid & 31;
    const int wm   = wid >> 1;
    const int wn   = wid & 1;
    const int m0   = blockIdx.x * 128;
    const int mode = mode_base + (blockIdx.y >> 3);
    const int n0   = (blockIdx.y & 7) * 64;
    const bool two = (mode < 2);

    const __half* __restrict__ Ah = g_Inh + (size_t)mode * IN_STRIDE;
    const __half* __restrict__ Al = g_Inl + (size_t)mode * IN_STRIDE;
    const __half* __restrict__ Bw = g_Wh  + (size_t)mode * 262144;
    const float* __restrict__ bias = (mode == 0) ? qb : (mode == 1) ? kb
                                   : (mode == 2) ? vb : ob;

    // stage layout: Ah 0-8K, Al 8-16K, B 16-20K (64B rows, swizzled)
#define GPREFETCH(K0, ST)                                                        \
    {                                                                            \
        uint32_t d0 = sb + (ST) * GS_STAGE;                                      \
        _Pragma("unroll")                                                        \
        for (int i = 0; i < 4; i++) {                                            \
            int idx = tid + 128 * i;                                             \
            int row = idx >> 2;                                                  \
            int seg = idx & 3;                                                   \
            cp16(d0 + row * 64 + ((seg ^ ((row >> 1) & 3)) << 4),                \
                 Ah + (size_t)(m0 + row) * 512 + (K0) + seg * 8);                \
        }                                                                        \
        if (two) {                                                               \
            _Pragma("unroll")                                                    \
            for (int i = 0; i < 4; i++) {                                        \
                int idx = tid + 128 * i;                                         \
                int row = idx >> 2;                                              \
                int seg = idx & 3;                                               \
                cp16(d0 + 8192 + row * 64 + ((seg ^ ((row >> 1) & 3)) << 4),     \
                     Al + (size_t)(m0 + row) * 512 + (K0) + seg * 8);            \
            }                                                                    \
        }                                                                        \
        _Pragma("unroll")                                                        \
        for (int i = 0; i < 2; i++) {                                            \
            int r2  = tid + 128 * i;                                             \
            int row = r2 >> 2;                                                   \
            int seg = r2 & 3;                                                    \
            cp16(d0 + 16384 + row * 64 + ((seg ^ ((row >> 1) & 3)) << 4),        \
                 Bw + (size_t)(n0 + row) * 512 + (K0) + seg * 8);                \
        }                                                                        \
    }

    GPREFETCH(0, 0);
    cp_commit();

    float acc[4][4][4];
#pragma unroll
    for (int i = 0; i < 4; i++)
#pragma unroll
        for (int j = 0; j < 4; j++)
#pragma unroll
            for (int r = 0; r < 4; r++) acc[i][j][r] = 0.f;

    const int tile = lane >> 3;
    const int r8   = lane & 7;

    for (int it = 0; it < 16; it++) {
        cp_wait<0>();
        __syncthreads();
        if (it + 1 < 16) {
            GPREFETCH((it + 1) * 32, (it + 1) & 1);
            cp_commit();
        }
        const uint32_t stg  = sb + (it & 1) * GS_STAGE;
        const uint32_t aAhi = stg;
        const uint32_t aAlo = stg + 8192;
        const uint32_t aB   = stg + 16384;

#pragma unroll
        for (int ks = 0; ks < 2; ks++) {
            const int k16 = ks * 16;
            const int arow_off = r8 + ((tile & 1) << 3);
            const int aseg = (k16 + ((tile >= 2) ? 8 : 0)) >> 3;
            const int brow_off = r8 + ((tile >> 1) << 3);
            const int bseg = (k16 + ((tile & 1) ? 8 : 0)) >> 3;

            uint32_t ah[4][4], bf[2][4];
#pragma unroll
            for (int mi = 0; mi < 4; mi++) {
                int row = wm * 64 + mi * 16 + arow_off;
                uint32_t off = (uint32_t)(row * 64 + ((aseg ^ ((row >> 1) & 3)) << 4));
                ldm_x4(ah[mi], aAhi + off);
            }
#pragma unroll
            for (int p = 0; p < 2; p++) {
                int row = wn * 32 + p * 16 + brow_off;
                uint32_t off = (uint32_t)(row * 64 + ((bseg ^ ((row >> 1) & 3)) << 4));
                ldm_x4(bf[p], aB + off);
            }

#pragma unroll
            for (int mi = 0; mi < 4; mi++)
#pragma unroll
                for (int ni = 0; ni < 4; ni++)
                    mma_fp16(acc[mi][ni], ah[mi], &bf[ni >> 1][(ni & 1) * 2]);

            if (two) {
                uint32_t al[4][4];
#pragma unroll
                for (int mi = 0; mi < 4; mi++) {
                    int row = wm * 64 + mi * 16 + arow_off;
                    uint32_t off = (uint32_t)(row * 64 + ((aseg ^ ((row >> 1) & 3)) << 4));
                    ldm_x4(al[mi], aAlo + off);
                }
#pragma unroll
                for (int mi = 0; mi < 4; mi++)
#pragma unroll
                    for (int ni = 0; ni < 4; ni++)
                        mma_fp16(acc[mi][ni], al[mi], &bf[ni >> 1][(ni & 1) * 2]);
            }
        }
    }

    const int mrb = m0 + wm * 64;
    const int ncb = n0 + wn * 32;
#pragma unroll
    for (int mi = 0; mi < 4; mi++) {
#pragma unroll
        for (int ni = 0; ni < 4; ni++) {
            int n = ncb + ni * 8 + (lane & 3) * 2;
            float2 bv = *(const float2*)&bias[n];
#pragma unroll
            for (int hf = 0; hf < 2; hf++) {
                int m = mrb + mi * 16 + (lane >> 2) + hf * 8;
                float c0 = acc[mi][ni][hf * 2 + 0] + bv.x;
                float c1 = acc[mi][ni][hf * 2 + 1] + bv.y;
                if (mode < 3) {
                    int bb = m & 1, s = m >> 1;
                    int hh = n >> 6, d = n & 63;
                    size_t addr = (((size_t)bb * NH + hh) * SEQ + s) * DH + d;
                    __half* C = (mode == 0) ? g_Qs : (mode == 1) ? g_Ks : g_Vs;
                    *(__half2*)&C[addr] =
                        __halves2half2(__float2half(c0), __float2half(c1));
                } else {
                    int bb = m >> 13, s = m & (SEQ - 1);
                    *(float2*)&Cout[(size_t)(s * BATCH + bb) * EMB + n] = make_float2(c0, c1);
                }
            }
        }
    }
#undef GPREFETCH
}

// ============================================================
// Attention v5 (R15-proven): pure fp16 (fp32 acc). 128 threads, 4 warps;
// warp = 16 q-rows x 64 keys. Smem 24KB: K0|K1|V (8KB each).
// Epilogue writes AO hi only (out-proj is single-term).
// ============================================================
#define AT_K0 0
#define AT_K1 8192
#define AT_V  16384

__device__ __forceinline__ int blk_of(int j, int nb, const int* __restrict__ ri) {
    if (j < NGLOB) return j;
    if (j < NGLOB + NWIN) return (nb + j - 3 + NBLK) & (NBLK - 1);
    return ri[nb * 3 + (j - 5)];
}

__global__ __launch_bounds__(128, 4)
void attn_mma(const int* __restrict__ rand_idx)
{
    __shared__ char smb[24576];
    const uint32_t sb = smem_u32(smb);

    const int nb  = blockIdx.x;
    const int bh  = blockIdx.y;
    const int tid = threadIdx.x;
    const int w    = tid >> 5;
    const int lane = tid & 31;
    const int tile = lane >> 3;
    const int r8   = lane & 7;
    const int sel  = lane >> 3;
    const int qrow = lane >> 2;
    const int qc   = (lane & 3) * 2;
    const size_t base = (size_t)bh * SEQ * DH;
    const float CC = 0.18033688011112042f;   // (1/8) * log2(e)

#define STAGE_S(DST, SRC, ROWBASE)                                               \
    {                                                                            \
        _Pragma("unroll")                                                        \
        for (int i = 0; i < 4; i++) {                                            \
            int idx = tid + 128 * i;                                             \
            int row = idx >> 3;                                                  \
            int seg = idx & 7;                                                   \
            cp16((DST) + row * 128 + ((seg ^ (row & 7)) << 4),                   \
                 (SRC) + (ROWBASE) + (size_t)row * 64 + seg * 8);                \
        }                                                                        \
    }

    // ---- preload: Q (into V region) + K(0) ----
    STAGE_S(sb + AT_V,  g_Qs, base + (size_t)nb * BLK * DH);
    STAGE_S(sb + AT_K0, g_Ks, base + (size_t)blk_of(0, nb, rand_idx) * BLK * DH);
    cp_commit();
    cp_wait<0>();
    __syncthreads();

    // ---- hoist Q fragments ----
    uint32_t qh[4][4];
#pragma unroll
    for (int ks = 0; ks < 4; ks++) {
        const int arow = 16 * w + r8 + ((tile & 1) << 3);
        const int aseg = ks * 2 + ((tile >> 1) & 1);
        const uint32_t aoff = (uint32_t)(arow * 128 + ((aseg ^ (arow & 7)) << 4));
        ldm_x4(qh[ks], sb + AT_V + aoff);
    }
    __syncthreads();   // Q region free -> V can load

    STAGE_S(sb + AT_V,  g_Vs, base + (size_t)blk_of(0, nb, rand_idx) * BLK * DH);
    cp_commit();
    STAGE_S(sb + AT_K1, g_Ks, base + (size_t)blk_of(1, nb, rand_idx) * BLK * DH);
    cp_commit();

    float of[8][4];
#pragma unroll
    for (int i = 0; i < 8; i++)
#pragma unroll
        for (int jj = 0; jj < 4; jj++) of[i][jj] = 0.f;
    float mst0 = -1e30f, mst1 = -1e30f, lst0 = 0.f, lst1 = 0.f;

    for (int j = 0; j < MBL; j++) {
        const uint32_t kbuf = sb + ((j & 1) ? AT_K1 : AT_K0);

        float sf[8][4];
#pragma unroll
        for (int nf = 0; nf < 8; nf++)
#pragma unroll
            for (int r = 0; r < 4; r++) sf[nf][r] = 0.f;

#pragma unroll
        for (int ks = 0; ks < 4; ks++) {
            uint32_t kh[4][4];
#pragma unroll
            for (int p = 0; p < 4; p++) {
                const int brow = 16 * p + r8 + ((tile >> 1) << 3);
                const int bseg = ks * 2 + (tile & 1);
                const uint32_t boff = (uint32_t)(brow * 128 + ((bseg ^ (brow & 7)) << 4));
                ldm_x4(kh[p], kbuf + boff);
            }
#pragma unroll
            for (int nf = 0; nf < 8; nf++)
                mma_fp16(sf[nf], qh[ks], &kh[nf >> 1][(nf & 1) * 2]);
        }

        float rmax0 = sf[0][0], rmax1 = sf[0][2];
#pragma unroll
        for (int nf = 0; nf < 8; nf++) {
            rmax0 = fmaxf(rmax0, fmaxf(sf[nf][0], sf[nf][1]));
            rmax1 = fmaxf(rmax1, fmaxf(sf[nf][2], sf[nf][3]));
        }
        rmax0 = fmaxf(rmax0, __shfl_xor_sync(0xffffffffu, rmax0, 1));
        rmax0 = fmaxf(rmax0, __shfl_xor_sync(0xffffffffu, rmax0, 2));
        rmax1 = fmaxf(rmax1, __shfl_xor_sync(0xffffffffu, rmax1, 1));
        rmax1 = fmaxf(rmax1, __shfl_xor_sync(0xffffffffu, rmax1, 2));
        const float mn0 = fmaxf(mst0, rmax0);
        const float mn1 = fmaxf(mst1, rmax1);
        const float al0 = exp2f((mst0 - mn0) * CC);
        const float al1 = exp2f((mst1 - mn1) * CC);

        float rsum0 = 0.f, rsum1 = 0.f;
        uint32_t pah[4][4];
#pragma unroll
        for (int t = 0; t < 4; t++) {
#pragma unroll
            for (int hl = 0; hl < 2; hl++) {
                int nf = 2 * t + hl;
                float p0 = exp2f((sf[nf][0] - mn0) * CC);
                float p1 = exp2f((sf[nf][1] - mn0) * CC);
                float p2 = exp2f((sf[nf][2] - mn1) * CC);
                float p3 = exp2f((sf[nf][3] - mn1) * CC);
                rsum0 += p0 + p1;
                rsum1 += p2 + p3;
                pah[t][2 * hl + 0] = pack_hf2(p0, p1);
                pah[t][2 * hl + 1] = pack_hf2(p2, p3);
            }
        }
        rsum0 += __shfl_xor_sync(0xffffffffu, rsum0, 1);
        rsum0 += __shfl_xor_sync(0xffffffffu, rsum0, 2);
        rsum1 += __shfl_xor_sync(0xffffffffu, rsum1, 1);
        rsum1 += __shfl_xor_sync(0xffffffffu, rsum1, 2);
        lst0 = lst0 * al0 + rsum0;
        lst1 = lst1 * al1 + rsum1;
        mst0 = mn0;
        mst1 = mn1;
#pragma unroll
        for (int nf = 0; nf < 8; nf++) {
            of[nf][0] *= al0; of[nf][1] *= al0;
            of[nf][2] *= al1; of[nf][3] *= al1;
        }

        if (j < MBL - 1) cp_wait<1>(); else cp_wait<0>();
        __syncthreads();

#pragma unroll
        for (int t = 0; t < 4; t++) {
            const int vkey = 16 * t + (lane & 7) + ((sel & 1) << 3);
#pragma unroll
            for (int g = 0; g < 4; g++) {
                const int vseg = 2 * g + (sel >> 1);
                const uint32_t voff = (uint32_t)(vkey * 128 + ((vseg ^ (vkey & 7)) << 4));
                uint32_t vh[4];
                ldm_x4t(vh, sb + AT_V + voff);
                mma_fp16(of[2 * g + 0], pah[t], &vh[0]);
                mma_fp16(of[2 * g + 1], pah[t], &vh[2]);
            }
        }

        if (j < MBL - 1) {
            cp_wait<0>();
            __syncthreads();
            size_t v_b = base + (size_t)blk_of(j + 1, nb, rand_idx) * BLK * DH;
            STAGE_S(sb + AT_V, g_Vs, v_b);
            cp_commit();
            if (j < MBL - 2) {
                size_t k_b = base + (size_t)blk_of(j + 2, nb, rand_idx) * BLK * DH;
                STAGE_S(sb + ((j & 1) ? AT_K1 : AT_K0), g_Ks, k_b);
                cp_commit();
            }
        }
    }

    // ---- epilogue: store normalized O as single fp16 (out-proj A operand) ----
    const int b = bh >> 3, h = bh & 7;
    const int r0 = 16 * w + qrow;
    const float inv0 = 1.f / lst0;
    const float inv1 = 1.f / lst1;
    __half* AOh = g_Inh + 3 * IN_STRIDE;
#pragma unroll
    for (int nf = 0; nf < 8; nf++) {
        int d = nf * 8 + qc;
        float v00 = of[nf][0] * inv0, v01 = of[nf][1] * inv0;
        float v10 = of[nf][2] * inv1, v11 = of[nf][3] * inv1;
        size_t a0 = (size_t)(b * SEQ + nb * BLK + r0) * EMB + h * DH + d;
        size_t a1 = (size_t)(b * SEQ + nb * BLK + r0 + 8) * EMB + h * DH + d;
        *(__half2*)&AOh[a0] = __halves2half2(__float2half(v00), __float2half(v01));
        *(__half2*)&AOh[a1] = __halves2half2(__float2half(v10), __float2half(v11));
    }
#undef STAGE_S
}

// ============================================================
extern "C" void kernel_launch(void* const* d_in, const int* in_sizes, int n_in,
                              void* d_out, int out_size)
{
    const float* query   = (const float*)d_in[0];
    const float* key_inp = (const float*)d_in[1];
    const float* value   = (const float*)d_in[2];
    const float* q_w     = (const float*)d_in[3];
    const float* k_w     = (const float*)d_in[4];
    const float* v_w     = (const float*)d_in[5];
    const float* q_b     = (const float*)d_in[6];
    const float* k_b     = (const float*)d_in[7];
    const float* v_b     = (const float*)d_in[8];
    const float* out_w   = (const float*)d_in[9];
    const float* out_b   = (const float*)d_in[10];
    const int*   rand_idx= (const int*)d_in[11];
    float* out = (float*)d_out;

    static bool attr_set = false;
    if (!attr_set) {
        cudaFuncSetAttribute(gemm_mma,
                             cudaFuncAttributeMaxDynamicSharedMemorySize, GS_SMEM);
        attr_set = true;
    }

    conv_all<<<8192, 256>>>(q_w, k_w, v_w, out_w, query, key_inp, value);

    dim3 gQKV(128, 24);
    gemm_mma<<<gQKV, 128, GS_SMEM>>>(q_b, k_b, v_b, out_b, out, 0);

    dim3 gAttn(NBLK, BATCH * NH);
    attn_mma<<<gAttn, 128>>>(rand_idx);

    dim3 gOut(128, 8);
    gemm_mma<<<gOut, 128, GS_SMEM>>>(q_b, k_b, v_b, out_b, out, 3);
}

// round 17
// speedup vs baseline: 3.0203x; 1.0903x over previous
#include <cuda_runtime.h>
#include <cuda_bf16.h>
#include <cuda_fp16.h>
#include <math.h>
#include <cstdint>

#define SEQ   8192
#define BATCH 2
#define EMB   512
#define NH    8
#define DH    64
#define NBLK  128      // SEQ / 64
#define BLK   64
#define MBL   8        // gathered blocks per query block
#define NGLOB 2
#define NWIN  3

#define IN_STRIDE ((size_t)16384 * 512)

// ---- device-global scratch (allocation-free) ----
// A-side activations, fp16 hi/lo: slots 0=q_in 1=k_in 2=v_in 3=attn_out
// (lo only consumed for slot 0 = Q projection)
__device__ __half g_Inh[4 * IN_STRIDE];
__device__ __half g_Inl[4 * IN_STRIDE];
// post-projection Q/K/V single fp16, [b][h][s][d]
__device__ __half g_Qs[(size_t)BATCH * NH * SEQ * DH];
__device__ __half g_Ks[(size_t)BATCH * NH * SEQ * DH];
__device__ __half g_Vs[(size_t)BATCH * NH * SEQ * DH];
// fp16 single weights: [mat][n][k], mat: 0=q 1=k 2=v 3=out
__device__ __half g_Wh[4u * 512u * 512u];

// ============================================================
// helpers (baseline PTX only)
// ============================================================
__device__ __forceinline__ uint32_t smem_u32(const void* p) {
    uint32_t a;
    asm("{ .reg .u64 t; cvta.to.shared.u64 t, %1; cvt.u32.u64 %0, t; }"
        : "=r"(a) : "l"(p));
    return a;
}
__device__ __forceinline__ void ldm_x4(uint32_t* r, uint32_t addr) {
    asm volatile("ldmatrix.sync.aligned.m8n8.x4.shared.b16 {%0,%1,%2,%3}, [%4];"
                 : "=r"(r[0]), "=r"(r[1]), "=r"(r[2]), "=r"(r[3]) : "r"(addr));
}
__device__ __forceinline__ void ldm_x4t(uint32_t* r, uint32_t addr) {
    asm volatile("ldmatrix.sync.aligned.m8n8.x4.trans.shared.b16 {%0,%1,%2,%3}, [%4];"
                 : "=r"(r[0]), "=r"(r[1]), "=r"(r[2]), "=r"(r[3]) : "r"(addr));
}
__device__ __forceinline__ void mma_fp16(float* d, const uint32_t* a, const uint32_t* b) {
    asm volatile(
        "mma.sync.aligned.m16n8k16.row.col.f32.f16.f16.f32 "
        "{%0,%1,%2,%3}, {%4,%5,%6,%7}, {%8,%9}, {%0,%1,%2,%3};"
        : "+f"(d[0]), "+f"(d[1]), "+f"(d[2]), "+f"(d[3])
        : "r"(a[0]), "r"(a[1]), "r"(a[2]), "r"(a[3]), "r"(b[0]), "r"(b[1]));
}
__device__ __forceinline__ void cp16(uint32_t dst, const void* src) {
    asm volatile("cp.async.cg.shared.global [%0], [%1], 16;" :: "r"(dst), "l"(src) : "memory");
}
__device__ __forceinline__ void cp_commit() {
    asm volatile("cp.async.commit_group;" ::: "memory");
}
template<int N> __device__ __forceinline__ void cp_wait() {
    asm volatile("cp.async.wait_group %0;" :: "n"(N) : "memory");
}
__device__ __forceinline__ uint32_t pack_hf2(float x, float y) {
    __half2 v = __halves2half2(__float2half(x), __float2half(y));
    return *(uint32_t*)&v;
}

// ============================================================
// Fused conversion: weights (fp32 -> single fp16, [mat][n][k]) +
// inputs (fp32 -> fp16; lo-term only for Q input).
// ============================================================
__global__ void conv_all(const float* __restrict__ qw, const float* __restrict__ kw,
                         const float* __restrict__ vw, const float* __restrict__ ow,
                         const float* __restrict__ qi, const float* __restrict__ ki,
                         const float* __restrict__ vi)
{
    const int bx = blockIdx.x;
    if (bx < 2048) {
        const int mat = bx >> 9;
        const int n   = bx & 511;
        const float* src = (mat == 0) ? qw : (mat == 1) ? kw : (mat == 2) ? vw : ow;
        for (int k = threadIdx.x; k < 512; k += 256) {
            float v;
            if (mat < 3) v = src[((size_t)(n >> 6) * 512 + k) * 64 + (n & 63)];
            else         v = src[(size_t)n * 512 + k];
            g_Wh[(size_t)mat * 262144 + (size_t)n * 512 + k] = __float2half(v);
        }
    } else {
        const int bi  = bx - 2048;
        const int mat = bi >> 11;
        const int blk = bi & 2047;
        const float* src = (mat == 0) ? qi : (mat == 1) ? ki : vi;
        __half* dh = g_Inh + (size_t)mat * IN_STRIDE;
        __half* dl = g_Inl + (size_t)mat * IN_STRIDE;
        const bool need_lo = (mat == 0);   // only Q projection is 2-term
#pragma unroll
        for (int i = 0; i < 4; i++) {
            size_t o4 = (size_t)blk * 1024 + i * 256 + threadIdx.x;
            float4 x = *(const float4*)&src[o4 * 4];
            __half h0 = __float2half(x.x), h1 = __float2half(x.y);
            __half h2 = __float2half(x.z), h3 = __float2half(x.w);
            *(__half2*)&dh[o4 * 4 + 0] = __halves2half2(h0, h1);
            *(__half2*)&dh[o4 * 4 + 2] = __halves2half2(h2, h3);
            if (need_lo) {
                __half l0 = __float2half(x.x - __half2float(h0));
                __half l1 = __float2half(x.y - __half2float(h1));
                __half l2 = __float2half(x.z - __half2float(h2));
                __half l3 = __float2half(x.w - __half2float(h3));
                *(__half2*)&dl[o4 * 4 + 0] = __halves2half2(l0, l1);
                *(__half2*)&dl[o4 * 4 + 2] = __halves2half2(l2, l3);
            }
        }
    }
}

// ============================================================
// HMMA GEMM: fp16, CTA 128x64, 128 thr, 4 CTAs/SM.
// Mode 0 (Q proj): 2-term A (hi/lo).  Modes 1-3 (K, V, out): single-term.
// Epilogue: modes 0-2 -> single fp16 Q/K/V; mode 3 -> fp32 out.
// ============================================================
#define GS_STAGE 20480
#define GS_SMEM  (2 * GS_STAGE)   // 40 KB

__global__ __launch_bounds__(128, 4)
void gemm_mma(const float* __restrict__ qb, const float* __restrict__ kb,
              const float* __restrict__ vb, const float* __restrict__ ob,
              float* __restrict__ Cout, int mode_base)
{
    extern __shared__ char gsm[];
    const uint32_t sb = smem_u32(gsm);
    const int tid  = threadIdx.x;
    const int wid  = tid >> 5;
    const int lane = tid & 31;
    const int wm   = wid >> 1;
    const int wn   = wid & 1;
    const int m0   = blockIdx.x * 128;
    const int mode = mode_base + (blockIdx.y >> 3);
    const int n0   = (blockIdx.y & 7) * 64;
    const bool two = (mode == 0);

    const __half* __restrict__ Ah = g_Inh + (size_t)mode * IN_STRIDE;
    const __half* __restrict__ Al = g_Inl + (size_t)mode * IN_STRIDE;
    const __half* __restrict__ Bw = g_Wh  + (size_t)mode * 262144;
    const float* __restrict__ bias = (mode == 0) ? qb : (mode == 1) ? kb
                                   : (mode == 2) ? vb : ob;

    // stage layout: Ah 0-8K, Al 8-16K, B 16-20K (64B rows, swizzled)
#define GPREFETCH(K0, ST)                                                        \
    {                                                                            \
        uint32_t d0 = sb + (ST) * GS_STAGE;                                      \
        _Pragma("unroll")                                                        \
        for (int i = 0; i < 4; i++) {                                            \
            int idx = tid + 128 * i;                                             \
            int row = idx >> 2;                                                  \
            int seg = idx & 3;                                                   \
            cp16(d0 + row * 64 + ((seg ^ ((row >> 1) & 3)) << 4),                \
                 Ah + (size_t)(m0 + row) * 512 + (K0) + seg * 8);                \
        }                                                                        \
        if (two) {                                                               \
            _Pragma("unroll")                                                    \
            for (int i = 0; i < 4; i++) {                                        \
                int idx = tid + 128 * i;                                         \
                int row = idx >> 2;                                              \
                int seg = idx & 3;                                               \
                cp16(d0 + 8192 + row * 64 + ((seg ^ ((row >> 1) & 3)) << 4),     \
                     Al + (size_t)(m0 + row) * 512 + (K0) + seg * 8);            \
            }                                                                    \
        }                                                                        \
        _Pragma("unroll")                                                        \
        for (int i = 0; i < 2; i++) {                                            \
            int r2  = tid + 128 * i;                                             \
            int row = r2 >> 2;                                                   \
            int seg = r2 & 3;                                                    \
            cp16(d0 + 16384 + row * 64 + ((seg ^ ((row >> 1) & 3)) << 4),        \
                 Bw + (size_t)(n0 + row) * 512 + (K0) + seg * 8);                \
        }                                                                        \
    }

    GPREFETCH(0, 0);
    cp_commit();

    float acc[4][4][4];
#pragma unroll
    for (int i = 0; i < 4; i++)
#pragma unroll
        for (int j = 0; j < 4; j++)
#pragma unroll
            for (int r = 0; r < 4; r++) acc[i][j][r] = 0.f;

    const int tile = lane >> 3;
    const int r8   = lane & 7;

    for (int it = 0; it < 16; it++) {
        cp_wait<0>();
        __syncthreads();
        if (it + 1 < 16) {
            GPREFETCH((it + 1) * 32, (it + 1) & 1);
            cp_commit();
        }
        const uint32_t stg  = sb + (it & 1) * GS_STAGE;
        const uint32_t aAhi = stg;
        const uint32_t aAlo = stg + 8192;
        const uint32_t aB   = stg + 16384;

#pragma unroll
        for (int ks = 0; ks < 2; ks++) {
            const int k16 = ks * 16;
            const int arow_off = r8 + ((tile & 1) << 3);
            const int aseg = (k16 + ((tile >= 2) ? 8 : 0)) >> 3;
            const int brow_off = r8 + ((tile >> 1) << 3);
            const int bseg = (k16 + ((tile & 1) ? 8 : 0)) >> 3;

            uint32_t ah[4][4], bf[2][4];
#pragma unroll
            for (int mi = 0; mi < 4; mi++) {
                int row = wm * 64 + mi * 16 + arow_off;
                uint32_t off = (uint32_t)(row * 64 + ((aseg ^ ((row >> 1) & 3)) << 4));
                ldm_x4(ah[mi], aAhi + off);
            }
#pragma unroll
            for (int p = 0; p < 2; p++) {
                int row = wn * 32 + p * 16 + brow_off;
                uint32_t off = (uint32_t)(row * 64 + ((bseg ^ ((row >> 1) & 3)) << 4));
                ldm_x4(bf[p], aB + off);
            }

#pragma unroll
            for (int mi = 0; mi < 4; mi++)
#pragma unroll
                for (int ni = 0; ni < 4; ni++)
                    mma_fp16(acc[mi][ni], ah[mi], &bf[ni >> 1][(ni & 1) * 2]);

            if (two) {
                uint32_t al[4][4];
#pragma unroll
                for (int mi = 0; mi < 4; mi++) {
                    int row = wm * 64 + mi * 16 + arow_off;
                    uint32_t off = (uint32_t)(row * 64 + ((aseg ^ ((row >> 1) & 3)) << 4));
                    ldm_x4(al[mi], aAlo + off);
                }
#pragma unroll
                for (int mi = 0; mi < 4; mi++)
#pragma unroll
                    for (int ni = 0; ni < 4; ni++)
                        mma_fp16(acc[mi][ni], al[mi], &bf[ni >> 1][(ni & 1) * 2]);
            }
        }
    }

    const int mrb = m0 + wm * 64;
    const int ncb = n0 + wn * 32;
#pragma unroll
    for (int mi = 0; mi < 4; mi++) {
#pragma unroll
        for (int ni = 0; ni < 4; ni++) {
            int n = ncb + ni * 8 + (lane & 3) * 2;
            float2 bv = *(const float2*)&bias[n];
#pragma unroll
            for (int hf = 0; hf < 2; hf++) {
                int m = mrb + mi * 16 + (lane >> 2) + hf * 8;
                float c0 = acc[mi][ni][hf * 2 + 0] + bv.x;
                float c1 = acc[mi][ni][hf * 2 + 1] + bv.y;
                if (mode < 3) {
                    int bb = m & 1, s = m >> 1;
                    int hh = n >> 6, d = n & 63;
                    size_t addr = (((size_t)bb * NH + hh) * SEQ + s) * DH + d;
                    __half* C = (mode == 0) ? g_Qs : (mode == 1) ? g_Ks : g_Vs;
                    *(__half2*)&C[addr] =
                        __halves2half2(__float2half(c0), __float2half(c1));
                } else {
                    int bb = m >> 13, s = m & (SEQ - 1);
                    *(float2*)&Cout[(size_t)(s * BATCH + bb) * EMB + n] = make_float2(c0, c1);
                }
            }
        }
    }
#undef GPREFETCH
}

// ============================================================
// Attention v5 (R15/R16-proven): pure fp16 (fp32 acc). 128 threads, 4 warps;
// warp = 16 q-rows x 64 keys. Smem 24KB: K0|K1|V (8KB each).
// ============================================================
#define AT_K0 0
#define AT_K1 8192
#define AT_V  16384

__device__ __forceinline__ int blk_of(int j, int nb, const int* __restrict__ ri) {
    if (j < NGLOB) return j;
    if (j < NGLOB + NWIN) return (nb + j - 3 + NBLK) & (NBLK - 1);
    return ri[nb * 3 + (j - 5)];
}

__global__ __launch_bounds__(128, 4)
void attn_mma(const int* __restrict__ rand_idx)
{
    __shared__ char smb[24576];
    const uint32_t sb = smem_u32(smb);

    const int nb  = blockIdx.x;
    const int bh  = blockIdx.y;
    const int tid = threadIdx.x;
    const int w    = tid >> 5;
    const int lane = tid & 31;
    const int tile = lane >> 3;
    const int r8   = lane & 7;
    const int sel  = lane >> 3;
    const int qrow = lane >> 2;
    const int qc   = (lane & 3) * 2;
    const size_t base = (size_t)bh * SEQ * DH;
    const float CC = 0.18033688011112042f;   // (1/8) * log2(e)

#define STAGE_S(DST, SRC, ROWBASE)                                               \
    {                                                                            \
        _Pragma("unroll")                                                        \
        for (int i = 0; i < 4; i++) {                                            \
            int idx = tid + 128 * i;                                             \
            int row = idx >> 3;                                                  \
            int seg = idx & 7;                                                   \
            cp16((DST) + row * 128 + ((seg ^ (row & 7)) << 4),                   \
                 (SRC) + (ROWBASE) + (size_t)row * 64 + seg * 8);                \
        }                                                                        \
    }

    // ---- preload: Q (into V region) + K(0) ----
    STAGE_S(sb + AT_V,  g_Qs, base + (size_t)nb * BLK * DH);
    STAGE_S(sb + AT_K0, g_Ks, base + (size_t)blk_of(0, nb, rand_idx) * BLK * DH);
    cp_commit();
    cp_wait<0>();
    __syncthreads();

    // ---- hoist Q fragments ----
    uint32_t qh[4][4];
#pragma unroll
    for (int ks = 0; ks < 4; ks++) {
        const int arow = 16 * w + r8 + ((tile & 1) << 3);
        const int aseg = ks * 2 + ((tile >> 1) & 1);
        const uint32_t aoff = (uint32_t)(arow * 128 + ((aseg ^ (arow & 7)) << 4));
        ldm_x4(qh[ks], sb + AT_V + aoff);
    }
    __syncthreads();   // Q region free -> V can load

    STAGE_S(sb + AT_V,  g_Vs, base + (size_t)blk_of(0, nb, rand_idx) * BLK * DH);
    cp_commit();
    STAGE_S(sb + AT_K1, g_Ks, base + (size_t)blk_of(1, nb, rand_idx) * BLK * DH);
    cp_commit();

    float of[8][4];
#pragma unroll
    for (int i = 0; i < 8; i++)
#pragma unroll
        for (int jj = 0; jj < 4; jj++) of[i][jj] = 0.f;
    float mst0 = -1e30f, mst1 = -1e30f, lst0 = 0.f, lst1 = 0.f;

    for (int j = 0; j < MBL; j++) {
        const uint32_t kbuf = sb + ((j & 1) ? AT_K1 : AT_K0);

        float sf[8][4];
#pragma unroll
        for (int nf = 0; nf < 8; nf++)
#pragma unroll
            for (int r = 0; r < 4; r++) sf[nf][r] = 0.f;

#pragma unroll
        for (int ks = 0; ks < 4; ks++) {
            uint32_t kh[4][4];
#pragma unroll
            for (int p = 0; p < 4; p++) {
                const int brow = 16 * p + r8 + ((tile >> 1) << 3);
                const int bseg = ks * 2 + (tile & 1);
                const uint32_t boff = (uint32_t)(brow * 128 + ((bseg ^ (brow & 7)) << 4));
                ldm_x4(kh[p], kbuf + boff);
            }
#pragma unroll
            for (int nf = 0; nf < 8; nf++)
                mma_fp16(sf[nf], qh[ks], &kh[nf >> 1][(nf & 1) * 2]);
        }

        float rmax0 = sf[0][0], rmax1 = sf[0][2];
#pragma unroll
        for (int nf = 0; nf < 8; nf++) {
            rmax0 = fmaxf(rmax0, fmaxf(sf[nf][0], sf[nf][1]));
            rmax1 = fmaxf(rmax1, fmaxf(sf[nf][2], sf[nf][3]));
        }
        rmax0 = fmaxf(rmax0, __shfl_xor_sync(0xffffffffu, rmax0, 1));
        rmax0 = fmaxf(rmax0, __shfl_xor_sync(0xffffffffu, rmax0, 2));
        rmax1 = fmaxf(rmax1, __shfl_xor_sync(0xffffffffu, rmax1, 1));
        rmax1 = fmaxf(rmax1, __shfl_xor_sync(0xffffffffu, rmax1, 2));
        const float mn0 = fmaxf(mst0, rmax0);
        const float mn1 = fmaxf(mst1, rmax1);
        const float al0 = exp2f((mst0 - mn0) * CC);
        const float al1 = exp2f((mst1 - mn1) * CC);

        float rsum0 = 0.f, rsum1 = 0.f;
        uint32_t pah[4][4];
#pragma unroll
        for (int t = 0; t < 4; t++) {
#pragma unroll
            for (int hl = 0; hl < 2; hl++) {
                int nf = 2 * t + hl;
                float p0 = exp2f((sf[nf][0] - mn0) * CC);
                float p1 = exp2f((sf[nf][1] - mn0) * CC);
                float p2 = exp2f((sf[nf][2] - mn1) * CC);
                float p3 = exp2f((sf[nf][3] - mn1) * CC);
                rsum0 += p0 + p1;
                rsum1 += p2 + p3;
                pah[t][2 * hl + 0] = pack_hf2(p0, p1);
                pah[t][2 * hl + 1] = pack_hf2(p2, p3);
            }
        }
        rsum0 += __shfl_xor_sync(0xffffffffu, rsum0, 1);
        rsum0 += __shfl_xor_sync(0xffffffffu, rsum0, 2);
        rsum1 += __shfl_xor_sync(0xffffffffu, rsum1, 1);
        rsum1 += __shfl_xor_sync(0xffffffffu, rsum1, 2);
        lst0 = lst0 * al0 + rsum0;
        lst1 = lst1 * al1 + rsum1;
        mst0 = mn0;
        mst1 = mn1;
#pragma unroll
        for (int nf = 0; nf < 8; nf++) {
            of[nf][0] *= al0; of[nf][1] *= al0;
            of[nf][2] *= al1; of[nf][3] *= al1;
        }

        if (j < MBL - 1) cp_wait<1>(); else cp_wait<0>();
        __syncthreads();

#pragma unroll
        for (int t = 0; t < 4; t++) {
            const int vkey = 16 * t + (lane & 7) + ((sel & 1) << 3);
#pragma unroll
            for (int g = 0; g < 4; g++) {
                const int vseg = 2 * g + (sel >> 1);
                const uint32_t voff = (uint32_t)(vkey * 128 + ((vseg ^ (vkey & 7)) << 4));
                uint32_t vh[4];
                ldm_x4t(vh, sb + AT_V + voff);
                mma_fp16(of[2 * g + 0], pah[t], &vh[0]);
                mma_fp16(of[2 * g + 1], pah[t], &vh[2]);
            }
        }

        if (j < MBL - 1) {
            cp_wait<0>();
            __syncthreads();
            size_t v_b = base + (size_t)blk_of(j + 1, nb, rand_idx) * BLK * DH;
            STAGE_S(sb + AT_V, g_Vs, v_b);
            cp_commit();
            if (j < MBL - 2) {
                size_t k_b = base + (size_t)blk_of(j + 2, nb, rand_idx) * BLK * DH;
                STAGE_S(sb + ((j & 1) ? AT_K1 : AT_K0), g_Ks, k_b);
                cp_commit();
            }
        }
    }

    // ---- epilogue: store normalized O as single fp16 (out-proj A operand) ----
    const int b = bh >> 3, h = bh & 7;
    const int r0 = 16 * w + qrow;
    const float inv0 = 1.f / lst0;
    const float inv1 = 1.f / lst1;
    __half* AOh = g_Inh + 3 * IN_STRIDE;
#pragma unroll
    for (int nf = 0; nf < 8; nf++) {
        int d = nf * 8 + qc;
        float v00 = of[nf][0] * inv0, v01 = of[nf][1] * inv0;
        float v10 = of[nf][2] * inv1, v11 = of[nf][3] * inv1;
        size_t a0 = (size_t)(b * SEQ + nb * BLK + r0) * EMB + h * DH + d;
        size_t a1 = (size_t)(b * SEQ + nb * BLK + r0 + 8) * EMB + h * DH + d;
        *(__half2*)&AOh[a0] = __halves2half2(__float2half(v00), __float2half(v01));
        *(__half2*)&AOh[a1] = __halves2half2(__float2half(v10), __float2half(v11));
    }
#undef STAGE_S
}

// ============================================================
extern "C" void kernel_launch(void* const* d_in, const int* in_sizes, int n_in,
                              void* d_out, int out_size)
{
    const float* query   = (const float*)d_in[0];
    const float* key_inp = (const float*)d_in[1];
    const float* value   = (const float*)d_in[2];
    const float* q_w     = (const float*)d_in[3];
    const float* k_w     = (const float*)d_in[4];
    const float* v_w     = (const float*)d_in[5];
    const float* q_b     = (const float*)d_in[6];
    const float* k_b     = (const float*)d_in[7];
    const float* v_b     = (const float*)d_in[8];
    const float* out_w   = (const float*)d_in[9];
    const float* out_b   = (const float*)d_in[10];
    const int*   rand_idx= (const int*)d_in[11];
    float* out = (float*)d_out;

    static bool attr_set = false;
    if (!attr_set) {
        cudaFuncSetAttribute(gemm_mma,
                             cudaFuncAttributeMaxDynamicSharedMemorySize, GS_SMEM);
        attr_set = true;
    }

    conv_all<<<8192, 256>>>(q_w, k_w, v_w, out_w, query, key_inp, value);

    dim3 gQKV(128, 24);
    gemm_mma<<<gQKV, 128, GS_SMEM>>>(q_b, k_b, v_b, out_b, out, 0);

    dim3 gAttn(NBLK, BATCH * NH);
    attn_mma<<<gAttn, 128>>>(rand_idx);

    dim3 gOut(128, 8);
    gemm_mma<<<gOut, 128, GS_SMEM>>>(q_b, k_b, v_b, out_b, out, 3);
}